// round 9
// baseline (speedup 1.0000x reference)
#include <cuda_runtime.h>
#include <cuda_bf16.h>
#include <math.h>
#include <stdint.h>

// ---------------------------------------------------------------------------
// KAN_GNN: GEMMs on mma.sync bf16x2 (fp32-class precision; compute_103 target
// so no tcgen05). CSR pull aggregation, fused mean+log_softmax epilogue.
// Schedule (round-7 winner): CSR build on side stream overlapped with GEMM1.
// GEMM producer: column-group-outer / power-inner chunk order so each x value
// is loaded from global ONCE and powered in registers (3x less A traffic).
// kan(x,w,b,c) == [x,x^2,x^3] @ W_eff + b,
//   W_eff[p*128+i][o] = (p==0 ? w[i][o] : 0) + 0.1*c[i][o][p]
// ---------------------------------------------------------------------------

#define MAX_NODES 100000
#define MAX_EDGES 1600000

__device__ __nv_bfloat16 g_w1hi[128 * 384];  // W_eff^T hi, [o][k]
__device__ __nv_bfloat16 g_w1lo[128 * 384];
__device__ __nv_bfloat16 g_w2hi[64 * 384];
__device__ __nv_bfloat16 g_w2lo[64 * 384];
__device__ float4 g_h1[(size_t)MAX_NODES * 32];   // 128 floats / node
__device__ float4 g_a1[(size_t)MAX_NODES * 32];
__device__ float4 g_h2[(size_t)MAX_NODES * 16];   // 64 floats / node
__device__ int    g_src[MAX_EDGES];
__device__ int    g_tgt[MAX_EDGES];
__device__ int    g_is64;
__device__ int    g_cnt[MAX_NODES];
__device__ int    g_fill[MAX_NODES];
__device__ int    g_rowptr[MAX_NODES + 1];
__device__ int    g_csr[MAX_EDGES];
__device__ int    g_blk[128];

// ---------------------------------------------------------------------------
// helpers
// ---------------------------------------------------------------------------
__device__ __forceinline__ uint32_t smem_u32(const void* p) {
    uint32_t a;
    asm("{ .reg .u64 t; cvta.to.shared.u64 t, %1; cvt.u32.u64 %0, t; }" : "=r"(a) : "l"(p));
    return a;
}
__device__ __forceinline__ void ldsm4(uint32_t r[4], uint32_t addr) {
    asm volatile("ldmatrix.sync.aligned.m8n8.x4.shared.b16 {%0,%1,%2,%3}, [%4];"
                 : "=r"(r[0]), "=r"(r[1]), "=r"(r[2]), "=r"(r[3]) : "r"(addr));
}
__device__ __forceinline__ void mma16816(float d[4], const uint32_t a[4], const uint32_t b[2]) {
    asm volatile(
        "mma.sync.aligned.m16n8k16.row.col.f32.bf16.bf16.f32 "
        "{%0,%1,%2,%3}, {%4,%5,%6,%7}, {%8,%9}, {%0,%1,%2,%3};"
        : "+f"(d[0]), "+f"(d[1]), "+f"(d[2]), "+f"(d[3])
        : "r"(a[0]), "r"(a[1]), "r"(a[2]), "r"(a[3]), "r"(b[0]), "r"(b[1]));
}
// split two floats into packed bf16 hi pair + bf16 lo pair
__device__ __forceinline__ void split2(float x, float y, uint32_t& hi, uint32_t& lo) {
    __nv_bfloat16 hx = __float2bfloat16_rn(x), hy = __float2bfloat16_rn(y);
    float rx = x - __bfloat162float(hx), ry = y - __bfloat162float(hy);
    __nv_bfloat16 lx = __float2bfloat16_rn(rx), ly = __float2bfloat16_rn(ry);
    hi = ((uint32_t)__bfloat16_as_ushort(hy) << 16) | (uint32_t)__bfloat16_as_ushort(hx);
    lo = ((uint32_t)__bfloat16_as_ushort(ly) << 16) | (uint32_t)__bfloat16_as_ushort(lx);
}
__device__ __forceinline__ void acc4(float4& a, const float4& v0, const float4& v1,
                                     const float4& v2, const float4& v3) {
    a.x += (v0.x + v1.x) + (v2.x + v3.x);
    a.y += (v0.y + v1.y) + (v2.y + v3.y);
    a.z += (v0.z + v1.z) + (v2.z + v3.z);
    a.w += (v0.w + v1.w) + (v2.w + v3.w);
}

// ---------------------------------------------------------------------------
// Edge dtype detection + fused convert/histogram
// ---------------------------------------------------------------------------
__global__ void detect_dtype(const int* __restrict__ buf) {
    if (threadIdx.x == 0 && blockIdx.x == 0) {
        int any = 0;
        for (int i = 1; i < 256; i += 2) any |= buf[i];
        g_is64 = (any == 0) ? 1 : 0;
    }
}

__global__ void zero_int2(int N) {
    int i = blockIdx.x * blockDim.x + threadIdx.x;
    if (i < N) { g_cnt[i] = 0; g_fill[i] = 0; }
}

__global__ void convert_hist(const void* __restrict__ ei, int E, int N) {
    int e = blockIdx.x * blockDim.x + threadIdx.x;
    if (e >= E) return;
    int s, t;
    if (g_is64) {
        const long long* p = (const long long*)ei;
        s = (int)p[e]; t = (int)p[e + E];
    } else {
        const int* p = (const int*)ei;
        s = p[e]; t = p[e + E];
    }
    g_src[e] = s;
    g_tgt[e] = t;
    if ((unsigned)t < (unsigned)N) atomicAdd(&g_cnt[t], 1);
}

// ---------------------------------------------------------------------------
// multi-block scan: rowptr[i+1] = sum cnt[0..i]
// ---------------------------------------------------------------------------
__global__ void scan_partials(int n) {
    __shared__ int sh[1024];
    int i = blockIdx.x * 1024 + threadIdx.x;
    sh[threadIdx.x] = (i < n) ? g_cnt[i] : 0;
    __syncthreads();
    for (int off = 1; off < 1024; off <<= 1) {
        int t = (threadIdx.x >= (unsigned)off) ? sh[threadIdx.x - off] : 0;
        __syncthreads();
        sh[threadIdx.x] += t;
        __syncthreads();
    }
    if (i < n) g_rowptr[i + 1] = sh[threadIdx.x];
    if (threadIdx.x == 1023) g_blk[blockIdx.x] = sh[1023];
}

__global__ void scan_blocks(int nb) {
    if (threadIdx.x == 0 && blockIdx.x == 0) {
        int s = 0;
        for (int b = 0; b < nb; b++) { int t = g_blk[b]; g_blk[b] = s; s += t; }
        g_rowptr[0] = 0;
    }
}

__global__ void add_offsets(int n) {
    int i = blockIdx.x * 1024 + threadIdx.x;
    if (i < n) g_rowptr[i + 1] += g_blk[blockIdx.x];
}

__global__ void build_csr(int E, int N) {
    int e = blockIdx.x * blockDim.x + threadIdx.x;
    if (e < E) {
        int t = g_tgt[e];
        int s = g_src[e];
        if ((unsigned)t < (unsigned)N && (unsigned)s < (unsigned)N) {
            int pos = g_rowptr[t] + atomicAdd(&g_fill[t], 1);
            if ((unsigned)pos < (unsigned)MAX_EDGES) g_csr[pos] = s;
        }
    }
}

// ---------------------------------------------------------------------------
// fused weights, transposed to [o][k], split bf16 hi/lo
// ---------------------------------------------------------------------------
__global__ void fuse_w1(const float* __restrict__ w1, const float* __restrict__ c1) {
    int idx = blockIdx.x * blockDim.x + threadIdx.x;
    if (idx < 384 * 128) {
        int k = idx >> 7, o = idx & 127;
        int i = k & 127, p = k >> 7;
        float v = 0.1f * c1[(i * 128 + o) * 3 + p];
        if (p == 0) v += w1[i * 128 + o];
        __nv_bfloat16 h = __float2bfloat16_rn(v);
        g_w1hi[o * 384 + k] = h;
        g_w1lo[o * 384 + k] = __float2bfloat16_rn(v - __bfloat162float(h));
    }
}
__global__ void fuse_w2(const float* __restrict__ w2, const float* __restrict__ c2) {
    int idx = blockIdx.x * blockDim.x + threadIdx.x;
    if (idx < 384 * 64) {
        int k = idx >> 6, o = idx & 63;
        int i = k & 127, p = k >> 7;
        float v = 0.1f * c2[(i * 64 + o) * 3 + p];
        if (p == 0) v += w2[i * 64 + o];
        __nv_bfloat16 h = __float2bfloat16_rn(v);
        g_w2hi[o * 384 + k] = h;
        g_w2lo[o * 384 + k] = __float2bfloat16_rn(v - __bfloat162float(h));
    }
}

// ---------------------------------------------------------------------------
// mma.sync bf16x2 GEMM: Out[128-tile x BN] = Aug(X)[tile x 384] @ Weff + bias.
// Chunk order: column-group outer, power inner -> k0(cc) = (cc%3)*128+(cc/3)*32.
// Each thread loads its 16 x-floats once per column group (xb), powers them in
// registers (xa *= xb, placed after compute so LDG latency is hidden).
// BK=32, double-buffered SMEM (pad-8 bf16 rows), 8 warps = 4(M) x 2(N).
// acc += Ahi*Bhi + Ahi*Blo + Alo*Bhi (fp32 accumulate in MMA).
// ---------------------------------------------------------------------------
template <int BN>
__global__ void __launch_bounds__(256) kan_gemm_mma(const float* __restrict__ Xp,
                                                    const float* __restrict__ bias, int N) {
    const int NT = BN / 16;                       // n8-tiles per warp
    const uint32_t ASZ = 128 * 40 * 2;            // bf16 tile, stride 40
    const uint32_t BSZ = (uint32_t)BN * 40 * 2;
    const uint32_t AHo = 0, BHo = 2 * ASZ;
    const uint32_t SBUF = 2 * ASZ + 2 * BSZ;

    extern __shared__ __align__(128) char smem[];
    uint32_t sb = smem_u32(smem);
    int tid = threadIdx.x, lane = tid & 31, wid = tid >> 5;
    int warp_m = wid & 3, warp_n = wid >> 2;
    int rowBase = blockIdx.x * 128;

    const float4* X4 = (BN == 128) ? (const float4*)Xp : g_a1;
    const __nv_bfloat16* WHp = (BN == 128) ? g_w1hi : g_w2hi;
    const __nv_bfloat16* WLp = (BN == 128) ? g_w1lo : g_w2lo;
    float* Out = (BN == 128) ? (float*)g_h1 : (float*)g_h2;

    // ---- producer indexing: thread -> (row, 16-col half) ----
    int rowl = tid >> 1, half = tid & 1;
    int nrow = rowBase + rowl;
    bool bact = rowl < BN;

    float4 xb[4];   // raw x for current column group
    float4 xa[4];   // current power of xb (what sts stores)
    uint4 wh0, wh1, wl0, wl1;

    auto loadX = [&](int cg) {
        if (nrow < N) {
            const float4* ptr = X4 + (size_t)nrow * 32 + cg * 8 + half * 4;
            xb[0] = ptr[0]; xb[1] = ptr[1]; xb[2] = ptr[2]; xb[3] = ptr[3];
        } else {
            xb[0] = xb[1] = xb[2] = xb[3] = make_float4(0.f, 0.f, 0.f, 0.f);
        }
    };
    auto setA = [&]() {
#pragma unroll
        for (int j = 0; j < 4; j++) xa[j] = xb[j];
    };
    auto mulA = [&]() {
#pragma unroll
        for (int j = 0; j < 4; j++) {
            xa[j].x *= xb[j].x; xa[j].y *= xb[j].y;
            xa[j].z *= xb[j].z; xa[j].w *= xb[j].w;
        }
    };
    auto loadB = [&](int cc) {
        if (!bact) return;
        int k0 = (cc % 3) * 128 + (cc / 3) * 32;
        size_t off = (size_t)rowl * 384 + k0 + half * 16;
        wh0 = *(const uint4*)(WHp + off); wh1 = *(const uint4*)(WHp + off + 8);
        wl0 = *(const uint4*)(WLp + off); wl1 = *(const uint4*)(WLp + off + 8);
    };
    auto sts = [&](int buf) {
        char* abase = smem + buf * SBUF + AHo + rowl * 80 + half * 32;
#pragma unroll
        for (int j = 0; j < 4; j++) {
            uint32_t h0, l0, h1, l1;
            split2(xa[j].x, xa[j].y, h0, l0);
            split2(xa[j].z, xa[j].w, h1, l1);
            *(uint2*)(abase + j * 8) = make_uint2(h0, h1);
            *(uint2*)(abase + ASZ + j * 8) = make_uint2(l0, l1);
        }
        if (bact) {
            char* bbase = smem + buf * SBUF + BHo + rowl * 80 + half * 32;
            *(uint4*)(bbase) = wh0;
            *(uint4*)(bbase + 16) = wh1;
            *(uint4*)(bbase + BSZ) = wl0;
            *(uint4*)(bbase + BSZ + 16) = wl1;
        }
    };

    // ---- consumer: ldmatrix lane offsets ----
    int lr = lane & 7, ls = lane >> 3;
    int a_row = lr + ((ls & 1) << 3);
    int a_k = (ls >> 1) << 3;
    int b_row = lr + ((ls >> 1) << 3);
    int b_k = (ls & 1) << 3;

    float acc[2][NT][4];
#pragma unroll
    for (int i = 0; i < 2; i++)
#pragma unroll
        for (int j = 0; j < NT; j++)
#pragma unroll
            for (int q = 0; q < 4; q++) acc[i][j][q] = 0.f;

    auto compute = [&](int buf) {
        uint32_t base = sb + buf * SBUF;
#pragma unroll
        for (int ks = 0; ks < 32; ks += 16) {
            uint32_t ah[2][4], al[2][4];
#pragma unroll
            for (int i = 0; i < 2; i++) {
                uint32_t ad = base + AHo + (uint32_t)(warp_m * 32 + i * 16 + a_row) * 80 +
                              (uint32_t)(ks + a_k) * 2;
                ldsm4(ah[i], ad);
                ldsm4(al[i], ad + ASZ);
            }
            uint32_t bh[NT][2], bl[NT][2];
#pragma unroll
            for (int j2 = 0; j2 < NT / 2; j2++) {
                uint32_t bd = base + BHo +
                              (uint32_t)(warp_n * (BN / 2) + j2 * 16 + b_row) * 80 +
                              (uint32_t)(ks + b_k) * 2;
                uint32_t t[4];
                ldsm4(t, bd);
                bh[2 * j2][0] = t[0]; bh[2 * j2][1] = t[1];
                bh[2 * j2 + 1][0] = t[2]; bh[2 * j2 + 1][1] = t[3];
                ldsm4(t, bd + BSZ);
                bl[2 * j2][0] = t[0]; bl[2 * j2][1] = t[1];
                bl[2 * j2 + 1][0] = t[2]; bl[2 * j2 + 1][1] = t[3];
            }
#pragma unroll
            for (int i = 0; i < 2; i++)
#pragma unroll
                for (int j = 0; j < NT; j++) {
                    mma16816(acc[i][j], ah[i], bh[j]);
                    mma16816(acc[i][j], ah[i], bl[j]);
                    mma16816(acc[i][j], al[i], bh[j]);
                }
        }
    };

    // ---- pipelined main loop: cc = cg*3 + p (cg outer, p inner) ----
    loadX(0);
    setA();
    loadB(0);
    for (int cc = 0; cc < 12; cc++) {
        int buf = cc & 1;
        sts(buf);
        __syncthreads();
        int nn = cc + 1;
        bool newcg = (nn % 3) == 0;
        if (nn < 12) {
            loadB(nn);
            if (newcg) loadX(nn / 3);
        }
        compute(buf);
        if (nn < 12) {
            if (newcg) setA();   // after compute: LDG latency hidden
            else mulA();
        }
        __syncthreads();
    }

    // ---- epilogue: bias (+relu), float2 stores ----
    int g = lane >> 2, t4 = lane & 3;
#pragma unroll
    for (int i = 0; i < 2; i++) {
        int m0 = rowBase + warp_m * 32 + i * 16 + g;
#pragma unroll
        for (int j = 0; j < NT; j++) {
            int col = warp_n * (BN / 2) + j * 8 + t4 * 2;
            float bx = bias[col], by = bias[col + 1];
            float v0 = acc[i][j][0] + bx, v1 = acc[i][j][1] + by;
            float v2 = acc[i][j][2] + bx, v3 = acc[i][j][3] + by;
            if (BN == 128) {
                v0 = fmaxf(v0, 0.f); v1 = fmaxf(v1, 0.f);
                v2 = fmaxf(v2, 0.f); v3 = fmaxf(v3, 0.f);
            }
            if (m0 < N) *(float2*)(Out + (size_t)m0 * BN + col) = make_float2(v0, v1);
            if (m0 + 8 < N) *(float2*)(Out + (size_t)(m0 + 8) * BN + col) = make_float2(v2, v3);
        }
    }
}

// ---------------------------------------------------------------------------
// gather-mean 1 (unroll-4): g_a1[n][:] = mean_{s in nbrs(n)} g_h1[s][:]
// ---------------------------------------------------------------------------
__global__ void gather_mean1(int N) {
    int g = blockIdx.x * 8 + ((int)threadIdx.x >> 5);
    int lane = (int)threadIdx.x & 31;
    if (g >= N) return;
    int beg = g_rowptr[g], end = g_rowptr[g + 1];
    float4 acc = make_float4(0.f, 0.f, 0.f, 0.f);
    int e = beg;
    for (; e + 4 <= end; e += 4) {
        int s0 = g_csr[e], s1 = g_csr[e + 1], s2 = g_csr[e + 2], s3 = g_csr[e + 3];
        float4 v0 = g_h1[(size_t)s0 * 32 + lane];
        float4 v1 = g_h1[(size_t)s1 * 32 + lane];
        float4 v2 = g_h1[(size_t)s2 * 32 + lane];
        float4 v3 = g_h1[(size_t)s3 * 32 + lane];
        acc4(acc, v0, v1, v2, v3);
    }
    for (; e < end; e++) {
        float4 v = g_h1[(size_t)g_csr[e] * 32 + lane];
        acc.x += v.x; acc.y += v.y; acc.z += v.z; acc.w += v.w;
    }
    float inv = 1.f / (float)max(end - beg, 1);
    acc.x *= inv; acc.y *= inv; acc.z *= inv; acc.w *= inv;
    g_a1[(size_t)g * 32 + lane] = acc;
}

// gather-mean 2 + log_softmax over 64 features; 16-lane group per node.
__global__ void gather_mean_lsm(float4* __restrict__ Out, int N) {
    int g = blockIdx.x * 16 + ((int)threadIdx.x >> 4);
    int lane = (int)threadIdx.x & 15;
    if (g >= N) return;
    int beg = g_rowptr[g], end = g_rowptr[g + 1];
    float4 acc = make_float4(0.f, 0.f, 0.f, 0.f);
    int e = beg;
    for (; e + 4 <= end; e += 4) {
        int s0 = g_csr[e], s1 = g_csr[e + 1], s2 = g_csr[e + 2], s3 = g_csr[e + 3];
        float4 v0 = g_h2[(size_t)s0 * 16 + lane];
        float4 v1 = g_h2[(size_t)s1 * 16 + lane];
        float4 v2 = g_h2[(size_t)s2 * 16 + lane];
        float4 v3 = g_h2[(size_t)s3 * 16 + lane];
        acc4(acc, v0, v1, v2, v3);
    }
    for (; e < end; e++) {
        float4 v = g_h2[(size_t)g_csr[e] * 16 + lane];
        acc.x += v.x; acc.y += v.y; acc.z += v.z; acc.w += v.w;
    }
    float inv = 1.f / (float)max(end - beg, 1);
    acc.x *= inv; acc.y *= inv; acc.z *= inv; acc.w *= inv;

    float m = fmaxf(fmaxf(acc.x, acc.y), fmaxf(acc.z, acc.w));
#pragma unroll
    for (int off = 8; off; off >>= 1) m = fmaxf(m, __shfl_xor_sync(0xffffffffu, m, off));
    float s = __expf(acc.x - m) + __expf(acc.y - m) + __expf(acc.z - m) + __expf(acc.w - m);
#pragma unroll
    for (int off = 8; off; off >>= 1) s += __shfl_xor_sync(0xffffffffu, s, off);
    float lse = m + __logf(s);
    acc.x -= lse; acc.y -= lse; acc.z -= lse; acc.w -= lse;
    Out[(size_t)g * 16 + lane] = acc;
}

// ---------------------------------------------------------------------------
extern "C" void kernel_launch(void* const* d_in, const int* in_sizes, int n_in,
                              void* d_out, int out_size) {
    const float* x  = (const float*)d_in[0];
    const void*  ei = d_in[1];
    const float* w1 = (const float*)d_in[2];
    const float* c1 = (const float*)d_in[4];
    const float* b1 = (const float*)d_in[3];
    const float* w2 = (const float*)d_in[5];
    const float* b2 = (const float*)d_in[6];
    const float* c2 = (const float*)d_in[7];
    float4* out     = (float4*)d_out;

    int N = in_sizes[0] / 128;
    int E = in_sizes[1] / 2;

    const int SMEM1 = 2 * (2 * 10240 + 2 * 128 * 80);  // 81920
    const int SMEM2 = 2 * (2 * 10240 + 2 * 64 * 80);   // 61440
    cudaFuncSetAttribute((const void*)kan_gemm_mma<128>,
                         cudaFuncAttributeMaxDynamicSharedMemorySize, SMEM1);
    cudaFuncSetAttribute((const void*)kan_gemm_mma<64>,
                         cudaFuncAttributeMaxDynamicSharedMemorySize, SMEM2);

    // fork-join: CSR build + fuse_w2 on side stream, fuse_w1+GEMM1 on main.
    // Stream/events created per call and deliberately not destroyed (capture).
    cudaStream_t s1;
    cudaStreamCreateWithFlags(&s1, cudaStreamNonBlocking);
    cudaEvent_t evF, evJ;
    cudaEventCreateWithFlags(&evF, cudaEventDisableTiming);
    cudaEventCreateWithFlags(&evJ, cudaEventDisableTiming);

    cudaEventRecord(evF, 0);
    cudaStreamWaitEvent(s1, evF, 0);

    // ---- side stream: fuse w2 + CSR chain ----
    fuse_w2<<<(384 * 64 + 255) / 256, 256, 0, s1>>>(w2, c2);
    zero_int2<<<(N + 255) / 256, 256, 0, s1>>>(N);
    detect_dtype<<<1, 32, 0, s1>>>((const int*)ei);
    convert_hist<<<(E + 255) / 256, 256, 0, s1>>>(ei, E, N);
    int nb = (N + 1023) / 1024;
    scan_partials<<<nb, 1024, 0, s1>>>(N);
    scan_blocks<<<1, 32, 0, s1>>>(nb);
    add_offsets<<<nb, 1024, 0, s1>>>(N);
    build_csr<<<(E + 255) / 256, 256, 0, s1>>>(E, N);
    cudaEventRecord(evJ, s1);

    // ---- main stream: fuse w1 + GEMM1 (overlapped with CSR) ----
    fuse_w1<<<(384 * 128 + 255) / 256, 256>>>(w1, c1);
    int tiles = (N + 127) / 128;
    kan_gemm_mma<128><<<tiles, 256, SMEM1>>>(x, b1, N);

    // join: gathers need both CSR and h1
    cudaStreamWaitEvent(0, evJ, 0);

    // aggregate 1 (mean)
    gather_mean1<<<(N + 7) / 8, 256>>>(N);

    // layer 2
    kan_gemm_mma<64><<<tiles, 256, SMEM2>>>(nullptr, b2, N);

    // aggregate 2 (mean) + log_softmax, straight into d_out
    gather_mean_lsm<<<(N + 15) / 16, 256>>>(out, N);
}

// round 10
// speedup vs baseline: 1.1072x; 1.1072x over previous
#include <cuda_runtime.h>
#include <cuda_bf16.h>
#include <cuda_fp16.h>
#include <math.h>
#include <stdint.h>

// ---------------------------------------------------------------------------
// KAN_GNN: GEMMs on mma.sync bf16x2 (fp32-class precision; compute_103 target
// so no tcgen05). CSR pull aggregation over fp16 message buffers (h1/h2 stored
// as __half -> half the random-row L2 traffic), fp32 accumulation everywhere.
// Schedule (round-7 winner): CSR build on side stream overlapped with GEMM1.
// kan(x,w,b,c) == [x,x^2,x^3] @ W_eff + b,
//   W_eff[p*128+i][o] = (p==0 ? w[i][o] : 0) + 0.1*c[i][o][p]
// ---------------------------------------------------------------------------

#define MAX_NODES 100000
#define MAX_EDGES 1600000

__device__ __nv_bfloat16 g_w1hi[128 * 384];  // W_eff^T hi, [o][k]
__device__ __nv_bfloat16 g_w1lo[128 * 384];
__device__ __nv_bfloat16 g_w2hi[64 * 384];
__device__ __nv_bfloat16 g_w2lo[64 * 384];
__device__ __half  g_h1h[(size_t)MAX_NODES * 128];  // fp16 messages, layer 1
__device__ __half  g_h2h[(size_t)MAX_NODES * 64];   // fp16 messages, layer 2
__device__ float4  g_a1[(size_t)MAX_NODES * 32];    // fp32 aggregated features
__device__ int    g_src[MAX_EDGES];
__device__ int    g_tgt[MAX_EDGES];
__device__ int    g_is64;
__device__ int    g_cnt[MAX_NODES];
__device__ int    g_fill[MAX_NODES];
__device__ int    g_rowptr[MAX_NODES + 1];
__device__ int    g_csr[MAX_EDGES];
__device__ int    g_blk[128];

// ---------------------------------------------------------------------------
// helpers
// ---------------------------------------------------------------------------
__device__ __forceinline__ uint32_t smem_u32(const void* p) {
    uint32_t a;
    asm("{ .reg .u64 t; cvta.to.shared.u64 t, %1; cvt.u32.u64 %0, t; }" : "=r"(a) : "l"(p));
    return a;
}
__device__ __forceinline__ void ldsm4(uint32_t r[4], uint32_t addr) {
    asm volatile("ldmatrix.sync.aligned.m8n8.x4.shared.b16 {%0,%1,%2,%3}, [%4];"
                 : "=r"(r[0]), "=r"(r[1]), "=r"(r[2]), "=r"(r[3]) : "r"(addr));
}
__device__ __forceinline__ void mma16816(float d[4], const uint32_t a[4], const uint32_t b[2]) {
    asm volatile(
        "mma.sync.aligned.m16n8k16.row.col.f32.bf16.bf16.f32 "
        "{%0,%1,%2,%3}, {%4,%5,%6,%7}, {%8,%9}, {%0,%1,%2,%3};"
        : "+f"(d[0]), "+f"(d[1]), "+f"(d[2]), "+f"(d[3])
        : "r"(a[0]), "r"(a[1]), "r"(a[2]), "r"(a[3]), "r"(b[0]), "r"(b[1]));
}
// split two floats into packed bf16 hi pair + bf16 lo pair
__device__ __forceinline__ void split2(float x, float y, uint32_t& hi, uint32_t& lo) {
    __nv_bfloat16 hx = __float2bfloat16_rn(x), hy = __float2bfloat16_rn(y);
    float rx = x - __bfloat162float(hx), ry = y - __bfloat162float(hy);
    __nv_bfloat16 lx = __float2bfloat16_rn(rx), ly = __float2bfloat16_rn(ry);
    hi = ((uint32_t)__bfloat16_as_ushort(hy) << 16) | (uint32_t)__bfloat16_as_ushort(hx);
    lo = ((uint32_t)__bfloat16_as_ushort(ly) << 16) | (uint32_t)__bfloat16_as_ushort(lx);
}
// accumulate 4 halves (uint2) into float4
__device__ __forceinline__ void accH(float4& a, uint2 v) {
    __half2 h0 = *(__half2*)&v.x, h1 = *(__half2*)&v.y;
    float2 f0 = __half22float2(h0), f1 = __half22float2(h1);
    a.x += f0.x; a.y += f0.y; a.z += f1.x; a.w += f1.y;
}

// ---------------------------------------------------------------------------
// Edge dtype detection + fused convert/histogram
// ---------------------------------------------------------------------------
__global__ void detect_dtype(const int* __restrict__ buf) {
    if (threadIdx.x == 0 && blockIdx.x == 0) {
        int any = 0;
        for (int i = 1; i < 256; i += 2) any |= buf[i];
        g_is64 = (any == 0) ? 1 : 0;
    }
}

__global__ void zero_int2(int N) {
    int i = blockIdx.x * blockDim.x + threadIdx.x;
    if (i < N) { g_cnt[i] = 0; g_fill[i] = 0; }
}

__global__ void convert_hist(const void* __restrict__ ei, int E, int N) {
    int e = blockIdx.x * blockDim.x + threadIdx.x;
    if (e >= E) return;
    int s, t;
    if (g_is64) {
        const long long* p = (const long long*)ei;
        s = (int)p[e]; t = (int)p[e + E];
    } else {
        const int* p = (const int*)ei;
        s = p[e]; t = p[e + E];
    }
    g_src[e] = s;
    g_tgt[e] = t;
    if ((unsigned)t < (unsigned)N) atomicAdd(&g_cnt[t], 1);
}

// ---------------------------------------------------------------------------
// multi-block scan: rowptr[i+1] = sum cnt[0..i]
// ---------------------------------------------------------------------------
__global__ void scan_partials(int n) {
    __shared__ int sh[1024];
    int i = blockIdx.x * 1024 + threadIdx.x;
    sh[threadIdx.x] = (i < n) ? g_cnt[i] : 0;
    __syncthreads();
    for (int off = 1; off < 1024; off <<= 1) {
        int t = (threadIdx.x >= (unsigned)off) ? sh[threadIdx.x - off] : 0;
        __syncthreads();
        sh[threadIdx.x] += t;
        __syncthreads();
    }
    if (i < n) g_rowptr[i + 1] = sh[threadIdx.x];
    if (threadIdx.x == 1023) g_blk[blockIdx.x] = sh[1023];
}

__global__ void scan_blocks(int nb) {
    if (threadIdx.x == 0 && blockIdx.x == 0) {
        int s = 0;
        for (int b = 0; b < nb; b++) { int t = g_blk[b]; g_blk[b] = s; s += t; }
        g_rowptr[0] = 0;
    }
}

__global__ void add_offsets(int n) {
    int i = blockIdx.x * 1024 + threadIdx.x;
    if (i < n) g_rowptr[i + 1] += g_blk[blockIdx.x];
}

__global__ void build_csr(int E, int N) {
    int e = blockIdx.x * blockDim.x + threadIdx.x;
    if (e < E) {
        int t = g_tgt[e];
        int s = g_src[e];
        if ((unsigned)t < (unsigned)N && (unsigned)s < (unsigned)N) {
            int pos = g_rowptr[t] + atomicAdd(&g_fill[t], 1);
            if ((unsigned)pos < (unsigned)MAX_EDGES) g_csr[pos] = s;
        }
    }
}

// ---------------------------------------------------------------------------
// fused weights, transposed to [o][k], split bf16 hi/lo (both layers)
// ---------------------------------------------------------------------------
__global__ void fuse_weights_t(const float* __restrict__ w1, const float* __restrict__ c1,
                               const float* __restrict__ w2, const float* __restrict__ c2) {
    int idx = blockIdx.x * blockDim.x + threadIdx.x;
    const int T1 = 384 * 128;
    const int T2 = 384 * 64;
    if (idx < T1) {
        int k = idx >> 7, o = idx & 127;
        int i = k & 127, p = k >> 7;
        float v = 0.1f * c1[(i * 128 + o) * 3 + p];
        if (p == 0) v += w1[i * 128 + o];
        __nv_bfloat16 h = __float2bfloat16_rn(v);
        g_w1hi[o * 384 + k] = h;
        g_w1lo[o * 384 + k] = __float2bfloat16_rn(v - __bfloat162float(h));
    } else if (idx < T1 + T2) {
        int j = idx - T1;
        int k = j >> 6, o = j & 63;
        int i = k & 127, p = k >> 7;
        float v = 0.1f * c2[(i * 64 + o) * 3 + p];
        if (p == 0) v += w2[i * 64 + o];
        __nv_bfloat16 h = __float2bfloat16_rn(v);
        g_w2hi[o * 384 + k] = h;
        g_w2lo[o * 384 + k] = __float2bfloat16_rn(v - __bfloat162float(h));
    }
}

// ---------------------------------------------------------------------------
// mma.sync bf16x2 GEMM: Out[128-tile x BN] = Aug(X)[tile x 384] @ Weff + bias.
// (round-7 validated config) BK=32, double-buffered SMEM (pad-8 bf16 rows),
// 8 warps = 4(M) x 2(N). acc += Ahi*Bhi + Ahi*Blo + Alo*Bhi.
// Output stored as fp16 (__half2 stores) for cheap downstream gathers.
// ---------------------------------------------------------------------------
template <int BN>
__global__ void __launch_bounds__(256) kan_gemm_mma(const float* __restrict__ Xp,
                                                    const float* __restrict__ bias, int N) {
    const int NT = BN / 16;                       // n8-tiles per warp
    const uint32_t ASZ = 128 * 40 * 2;            // bf16 tile, stride 40
    const uint32_t BSZ = (uint32_t)BN * 40 * 2;
    const uint32_t AHo = 0, BHo = 2 * ASZ;
    const uint32_t SBUF = 2 * ASZ + 2 * BSZ;

    extern __shared__ __align__(128) char smem[];
    uint32_t sb = smem_u32(smem);
    int tid = threadIdx.x, lane = tid & 31, wid = tid >> 5;
    int warp_m = wid & 3, warp_n = wid >> 2;
    int rowBase = blockIdx.x * 128;

    const float4* X4 = (BN == 128) ? (const float4*)Xp : g_a1;
    const __nv_bfloat16* WHp = (BN == 128) ? g_w1hi : g_w2hi;
    const __nv_bfloat16* WLp = (BN == 128) ? g_w1lo : g_w2lo;
    __half* Out = (BN == 128) ? g_h1h : g_h2h;

    // ---- producer indexing: thread -> (row, 16-col half) ----
    int rowl = tid >> 1, half = tid & 1;
    int nrow = rowBase + rowl;
    bool bact = rowl < BN;

    float4 xa[4];
    uint4 wh0, wh1, wl0, wl1;

    auto loadA = [&](int c) {
        int p = c >> 2;
        int i0 = (c & 3) * 32 + half * 16;
        if (nrow < N) {
            const float4* ptr = X4 + (size_t)nrow * 32 + (i0 >> 2);
            xa[0] = ptr[0]; xa[1] = ptr[1]; xa[2] = ptr[2]; xa[3] = ptr[3];
        } else {
            xa[0] = xa[1] = xa[2] = xa[3] = make_float4(0.f, 0.f, 0.f, 0.f);
        }
        if (p == 1) {
#pragma unroll
            for (int j = 0; j < 4; j++) {
                xa[j].x *= xa[j].x; xa[j].y *= xa[j].y;
                xa[j].z *= xa[j].z; xa[j].w *= xa[j].w;
            }
        } else if (p == 2) {
#pragma unroll
            for (int j = 0; j < 4; j++) {
                xa[j].x = xa[j].x * xa[j].x * xa[j].x;
                xa[j].y = xa[j].y * xa[j].y * xa[j].y;
                xa[j].z = xa[j].z * xa[j].z * xa[j].z;
                xa[j].w = xa[j].w * xa[j].w * xa[j].w;
            }
        }
    };
    auto loadB = [&](int c) {
        if (!bact) return;
        size_t off = (size_t)rowl * 384 + c * 32 + half * 16;
        wh0 = *(const uint4*)(WHp + off); wh1 = *(const uint4*)(WHp + off + 8);
        wl0 = *(const uint4*)(WLp + off); wl1 = *(const uint4*)(WLp + off + 8);
    };
    auto sts = [&](int buf) {
        char* abase = smem + buf * SBUF + AHo + rowl * 80 + half * 32;
#pragma unroll
        for (int j = 0; j < 4; j++) {
            uint32_t h0, l0, h1, l1;
            split2(xa[j].x, xa[j].y, h0, l0);
            split2(xa[j].z, xa[j].w, h1, l1);
            *(uint2*)(abase + j * 8) = make_uint2(h0, h1);
            *(uint2*)(abase + ASZ + j * 8) = make_uint2(l0, l1);
        }
        if (bact) {
            char* bbase = smem + buf * SBUF + BHo + rowl * 80 + half * 32;
            *(uint4*)(bbase) = wh0;
            *(uint4*)(bbase + 16) = wh1;
            *(uint4*)(bbase + BSZ) = wl0;
            *(uint4*)(bbase + BSZ + 16) = wl1;
        }
    };

    // ---- consumer: ldmatrix lane offsets ----
    int lr = lane & 7, ls = lane >> 3;
    int a_row = lr + ((ls & 1) << 3);
    int a_k = (ls >> 1) << 3;
    int b_row = lr + ((ls >> 1) << 3);
    int b_k = (ls & 1) << 3;

    float acc[2][NT][4];
#pragma unroll
    for (int i = 0; i < 2; i++)
#pragma unroll
        for (int j = 0; j < NT; j++)
#pragma unroll
            for (int q = 0; q < 4; q++) acc[i][j][q] = 0.f;

    auto compute = [&](int buf) {
        uint32_t base = sb + buf * SBUF;
#pragma unroll
        for (int ks = 0; ks < 32; ks += 16) {
            uint32_t ah[2][4], al[2][4];
#pragma unroll
            for (int i = 0; i < 2; i++) {
                uint32_t ad = base + AHo + (uint32_t)(warp_m * 32 + i * 16 + a_row) * 80 +
                              (uint32_t)(ks + a_k) * 2;
                ldsm4(ah[i], ad);
                ldsm4(al[i], ad + ASZ);
            }
            uint32_t bh[NT][2], bl[NT][2];
#pragma unroll
            for (int j2 = 0; j2 < NT / 2; j2++) {
                uint32_t bd = base + BHo +
                              (uint32_t)(warp_n * (BN / 2) + j2 * 16 + b_row) * 80 +
                              (uint32_t)(ks + b_k) * 2;
                uint32_t t[4];
                ldsm4(t, bd);
                bh[2 * j2][0] = t[0]; bh[2 * j2][1] = t[1];
                bh[2 * j2 + 1][0] = t[2]; bh[2 * j2 + 1][1] = t[3];
                ldsm4(t, bd + BSZ);
                bl[2 * j2][0] = t[0]; bl[2 * j2][1] = t[1];
                bl[2 * j2 + 1][0] = t[2]; bl[2 * j2 + 1][1] = t[3];
            }
#pragma unroll
            for (int i = 0; i < 2; i++)
#pragma unroll
                for (int j = 0; j < NT; j++) {
                    mma16816(acc[i][j], ah[i], bh[j]);
                    mma16816(acc[i][j], ah[i], bl[j]);
                    mma16816(acc[i][j], al[i], bh[j]);
                }
        }
    };

    // ---- pipelined main loop over 12 K-chunks ----
    loadA(0); loadB(0);
    for (int c = 0; c < 12; c++) {
        int buf = c & 1;
        sts(buf);
        __syncthreads();
        if (c < 11) { loadA(c + 1); loadB(c + 1); }
        compute(buf);
        __syncthreads();
    }

    // ---- epilogue: bias (+relu), fp16 (__half2) stores ----
    int g = lane >> 2, t4 = lane & 3;
#pragma unroll
    for (int i = 0; i < 2; i++) {
        int m0 = rowBase + warp_m * 32 + i * 16 + g;
#pragma unroll
        for (int j = 0; j < NT; j++) {
            int col = warp_n * (BN / 2) + j * 8 + t4 * 2;
            float bx = bias[col], by = bias[col + 1];
            float v0 = acc[i][j][0] + bx, v1 = acc[i][j][1] + by;
            float v2 = acc[i][j][2] + bx, v3 = acc[i][j][3] + by;
            if (BN == 128) {
                v0 = fmaxf(v0, 0.f); v1 = fmaxf(v1, 0.f);
                v2 = fmaxf(v2, 0.f); v3 = fmaxf(v3, 0.f);
            }
            if (m0 < N)
                *(__half2*)(Out + (size_t)m0 * BN + col) = __floats2half2_rn(v0, v1);
            if (m0 + 8 < N)
                *(__half2*)(Out + (size_t)(m0 + 8) * BN + col) = __floats2half2_rn(v2, v3);
        }
    }
}

// ---------------------------------------------------------------------------
// gather-mean 1 (unroll-4, fp16 rows): a1[n][:] = mean_{s in nbrs(n)} h1[s][:]
// 32 lanes per node, each lane owns 4 halves (uint2 = 8B); row = 256B.
// ---------------------------------------------------------------------------
__global__ void gather_mean1(int N) {
    int g = blockIdx.x * 8 + ((int)threadIdx.x >> 5);
    int lane = (int)threadIdx.x & 31;
    if (g >= N) return;
    const uint2* H = (const uint2*)g_h1h;   // 32 uint2 per row
    int beg = g_rowptr[g], end = g_rowptr[g + 1];
    float4 acc = make_float4(0.f, 0.f, 0.f, 0.f);
    int e = beg;
    for (; e + 4 <= end; e += 4) {
        int s0 = g_csr[e], s1 = g_csr[e + 1], s2 = g_csr[e + 2], s3 = g_csr[e + 3];
        uint2 v0 = H[(size_t)s0 * 32 + lane];
        uint2 v1 = H[(size_t)s1 * 32 + lane];
        uint2 v2 = H[(size_t)s2 * 32 + lane];
        uint2 v3 = H[(size_t)s3 * 32 + lane];
        accH(acc, v0); accH(acc, v1); accH(acc, v2); accH(acc, v3);
    }
    for (; e < end; e++) accH(acc, H[(size_t)g_csr[e] * 32 + lane]);
    float inv = 1.f / (float)max(end - beg, 1);
    acc.x *= inv; acc.y *= inv; acc.z *= inv; acc.w *= inv;
    g_a1[(size_t)g * 32 + lane] = acc;
}

// gather-mean 2 + log_softmax (fp16 rows); 16 lanes per node, row = 128B.
__global__ void gather_mean_lsm(float4* __restrict__ Out, int N) {
    int g = blockIdx.x * 16 + ((int)threadIdx.x >> 4);
    int lane = (int)threadIdx.x & 15;
    if (g >= N) return;
    const uint2* H = (const uint2*)g_h2h;   // 16 uint2 per row
    int beg = g_rowptr[g], end = g_rowptr[g + 1];
    float4 acc = make_float4(0.f, 0.f, 0.f, 0.f);
    int e = beg;
    for (; e + 4 <= end; e += 4) {
        int s0 = g_csr[e], s1 = g_csr[e + 1], s2 = g_csr[e + 2], s3 = g_csr[e + 3];
        uint2 v0 = H[(size_t)s0 * 16 + lane];
        uint2 v1 = H[(size_t)s1 * 16 + lane];
        uint2 v2 = H[(size_t)s2 * 16 + lane];
        uint2 v3 = H[(size_t)s3 * 16 + lane];
        accH(acc, v0); accH(acc, v1); accH(acc, v2); accH(acc, v3);
    }
    for (; e < end; e++) accH(acc, H[(size_t)g_csr[e] * 16 + lane]);
    float inv = 1.f / (float)max(end - beg, 1);
    acc.x *= inv; acc.y *= inv; acc.z *= inv; acc.w *= inv;

    float m = fmaxf(fmaxf(acc.x, acc.y), fmaxf(acc.z, acc.w));
#pragma unroll
    for (int off = 8; off; off >>= 1) m = fmaxf(m, __shfl_xor_sync(0xffffffffu, m, off));
    float s = __expf(acc.x - m) + __expf(acc.y - m) + __expf(acc.z - m) + __expf(acc.w - m);
#pragma unroll
    for (int off = 8; off; off >>= 1) s += __shfl_xor_sync(0xffffffffu, s, off);
    float lse = m + __logf(s);
    acc.x -= lse; acc.y -= lse; acc.z -= lse; acc.w -= lse;
    Out[(size_t)g * 16 + lane] = acc;
}

// ---------------------------------------------------------------------------
extern "C" void kernel_launch(void* const* d_in, const int* in_sizes, int n_in,
                              void* d_out, int out_size) {
    const float* x  = (const float*)d_in[0];
    const void*  ei = d_in[1];
    const float* w1 = (const float*)d_in[2];
    const float* b1 = (const float*)d_in[3];
    const float* c1 = (const float*)d_in[4];
    const float* w2 = (const float*)d_in[5];
    const float* b2 = (const float*)d_in[6];
    const float* c2 = (const float*)d_in[7];
    float4* out     = (float4*)d_out;

    int N = in_sizes[0] / 128;
    int E = in_sizes[1] / 2;

    const int SMEM1 = 2 * (2 * 10240 + 2 * 128 * 80);  // 81920
    const int SMEM2 = 2 * (2 * 10240 + 2 * 64 * 80);   // 61440
    cudaFuncSetAttribute((const void*)kan_gemm_mma<128>,
                         cudaFuncAttributeMaxDynamicSharedMemorySize, SMEM1);
    cudaFuncSetAttribute((const void*)kan_gemm_mma<64>,
                         cudaFuncAttributeMaxDynamicSharedMemorySize, SMEM2);

    // fork-join: CSR build on side stream, weights+GEMM1 on main (capture) stream.
    // Stream/events created per call and deliberately not destroyed (capture).
    cudaStream_t s1;
    cudaStreamCreateWithFlags(&s1, cudaStreamNonBlocking);
    cudaEvent_t evF, evJ;
    cudaEventCreateWithFlags(&evF, cudaEventDisableTiming);
    cudaEventCreateWithFlags(&evJ, cudaEventDisableTiming);

    cudaEventRecord(evF, 0);
    cudaStreamWaitEvent(s1, evF, 0);

    // ---- side stream: CSR chain ----
    zero_int2<<<(N + 255) / 256, 256, 0, s1>>>(N);
    detect_dtype<<<1, 32, 0, s1>>>((const int*)ei);
    convert_hist<<<(E + 255) / 256, 256, 0, s1>>>(ei, E, N);
    int nb = (N + 1023) / 1024;
    scan_partials<<<nb, 1024, 0, s1>>>(N);
    scan_blocks<<<1, 32, 0, s1>>>(nb);
    add_offsets<<<nb, 1024, 0, s1>>>(N);
    build_csr<<<(E + 255) / 256, 256, 0, s1>>>(E, N);
    cudaEventRecord(evJ, s1);

    // ---- main stream: weights + GEMM1 (overlapped with CSR) ----
    fuse_weights_t<<<(384 * 128 + 384 * 64 + 255) / 256, 256>>>(w1, c1, w2, c2);
    int tiles = (N + 127) / 128;
    kan_gemm_mma<128><<<tiles, 256, SMEM1>>>(x, b1, N);

    // join: gathers need both CSR and h1
    cudaStreamWaitEvent(0, evJ, 0);

    // aggregate 1 (mean)
    gather_mean1<<<(N + 7) / 8, 256>>>(N);

    // layer 2
    kan_gemm_mma<64><<<tiles, 256, SMEM2>>>(nullptr, b2, N);

    // aggregate 2 (mean) + log_softmax, straight into d_out
    gather_mean_lsm<<<(N + 15) / 16, 256>>>(out, N);
}

// round 11
// speedup vs baseline: 1.1867x; 1.0718x over previous
#include <cuda_runtime.h>
#include <cuda_bf16.h>
#include <cuda_fp16.h>
#include <math.h>
#include <stdint.h>

// ---------------------------------------------------------------------------
// KAN_GNN: GEMM1 on mma.sync bf16x2 (3-MMA split, fp32-class); GEMM2 on fp16
// mma.sync with exact fp16 A (2-MMA: Ah*Wh + Ah*Wl) -- its input a1 is already
// fp16-derived, so the split buys nothing. Messages h1/h2 and a1 stored fp16.
// CSR pull aggregation, fused mean+log_softmax epilogue; CSR build overlapped
// with GEMM1 on a side stream (round-7 schedule).
// kan(x,w,b,c) == [x,x^2,x^3] @ W_eff + b,
//   W_eff[p*128+i][o] = (p==0 ? w[i][o] : 0) + 0.1*c[i][o][p]
// ---------------------------------------------------------------------------

#define MAX_NODES 100000
#define MAX_EDGES 1600000

__device__ __nv_bfloat16 g_w1hi[128 * 384];  // W1_eff^T hi (bf16), [o][k]
__device__ __nv_bfloat16 g_w1lo[128 * 384];
__device__ __half g_w2hi[64 * 384];          // W2_eff^T hi (fp16), [o][k]
__device__ __half g_w2lo[64 * 384];          // residual (fp16)
__device__ __half g_h1h[(size_t)MAX_NODES * 128];  // fp16 messages, layer 1
__device__ __half g_h2h[(size_t)MAX_NODES * 64];   // fp16 messages, layer 2
__device__ __half g_a1h[(size_t)MAX_NODES * 128];  // fp16 aggregated features
__device__ int    g_src[MAX_EDGES];
__device__ int    g_tgt[MAX_EDGES];
__device__ int    g_is64;
__device__ int    g_cnt[MAX_NODES];
__device__ int    g_fill[MAX_NODES];
__device__ int    g_rowptr[MAX_NODES + 1];
__device__ int    g_csr[MAX_EDGES];
__device__ int    g_blk[128];

// ---------------------------------------------------------------------------
// helpers
// ---------------------------------------------------------------------------
__device__ __forceinline__ uint32_t smem_u32(const void* p) {
    uint32_t a;
    asm("{ .reg .u64 t; cvta.to.shared.u64 t, %1; cvt.u32.u64 %0, t; }" : "=r"(a) : "l"(p));
    return a;
}
__device__ __forceinline__ void ldsm4(uint32_t r[4], uint32_t addr) {
    asm volatile("ldmatrix.sync.aligned.m8n8.x4.shared.b16 {%0,%1,%2,%3}, [%4];"
                 : "=r"(r[0]), "=r"(r[1]), "=r"(r[2]), "=r"(r[3]) : "r"(addr));
}
__device__ __forceinline__ void mma16816(float d[4], const uint32_t a[4], const uint32_t b[2]) {
    asm volatile(
        "mma.sync.aligned.m16n8k16.row.col.f32.bf16.bf16.f32 "
        "{%0,%1,%2,%3}, {%4,%5,%6,%7}, {%8,%9}, {%0,%1,%2,%3};"
        : "+f"(d[0]), "+f"(d[1]), "+f"(d[2]), "+f"(d[3])
        : "r"(a[0]), "r"(a[1]), "r"(a[2]), "r"(a[3]), "r"(b[0]), "r"(b[1]));
}
__device__ __forceinline__ void mma16816h(float d[4], const uint32_t a[4], const uint32_t b[2]) {
    asm volatile(
        "mma.sync.aligned.m16n8k16.row.col.f32.f16.f16.f32 "
        "{%0,%1,%2,%3}, {%4,%5,%6,%7}, {%8,%9}, {%0,%1,%2,%3};"
        : "+f"(d[0]), "+f"(d[1]), "+f"(d[2]), "+f"(d[3])
        : "r"(a[0]), "r"(a[1]), "r"(a[2]), "r"(a[3]), "r"(b[0]), "r"(b[1]));
}
// split two floats into packed bf16 hi pair + bf16 lo pair
__device__ __forceinline__ void split2(float x, float y, uint32_t& hi, uint32_t& lo) {
    __nv_bfloat16 hx = __float2bfloat16_rn(x), hy = __float2bfloat16_rn(y);
    float rx = x - __bfloat162float(hx), ry = y - __bfloat162float(hy);
    __nv_bfloat16 lx = __float2bfloat16_rn(rx), ly = __float2bfloat16_rn(ry);
    hi = ((uint32_t)__bfloat16_as_ushort(hy) << 16) | (uint32_t)__bfloat16_as_ushort(hx);
    lo = ((uint32_t)__bfloat16_as_ushort(ly) << 16) | (uint32_t)__bfloat16_as_ushort(lx);
}
__device__ __forceinline__ uint32_t pack2h(float x, float y) {
    __half2 h = __floats2half2_rn(x, y);
    return *(uint32_t*)&h;
}
// accumulate 4 halves (uint2) into float4
__device__ __forceinline__ void accH(float4& a, uint2 v) {
    __half2 h0 = *(__half2*)&v.x, h1 = *(__half2*)&v.y;
    float2 f0 = __half22float2(h0), f1 = __half22float2(h1);
    a.x += f0.x; a.y += f0.y; a.z += f1.x; a.w += f1.y;
}

// ---------------------------------------------------------------------------
// Edge dtype detection + fused convert/histogram
// ---------------------------------------------------------------------------
__global__ void detect_dtype(const int* __restrict__ buf) {
    if (threadIdx.x == 0 && blockIdx.x == 0) {
        int any = 0;
        for (int i = 1; i < 256; i += 2) any |= buf[i];
        g_is64 = (any == 0) ? 1 : 0;
    }
}

__global__ void zero_int2(int N) {
    int i = blockIdx.x * blockDim.x + threadIdx.x;
    if (i < N) { g_cnt[i] = 0; g_fill[i] = 0; }
}

__global__ void convert_hist(const void* __restrict__ ei, int E, int N) {
    int e = blockIdx.x * blockDim.x + threadIdx.x;
    if (e >= E) return;
    int s, t;
    if (g_is64) {
        const long long* p = (const long long*)ei;
        s = (int)p[e]; t = (int)p[e + E];
    } else {
        const int* p = (const int*)ei;
        s = p[e]; t = p[e + E];
    }
    g_src[e] = s;
    g_tgt[e] = t;
    if ((unsigned)t < (unsigned)N) atomicAdd(&g_cnt[t], 1);
}

// ---------------------------------------------------------------------------
// multi-block scan: rowptr[i+1] = sum cnt[0..i]
// ---------------------------------------------------------------------------
__global__ void scan_partials(int n) {
    __shared__ int sh[1024];
    int i = blockIdx.x * 1024 + threadIdx.x;
    sh[threadIdx.x] = (i < n) ? g_cnt[i] : 0;
    __syncthreads();
    for (int off = 1; off < 1024; off <<= 1) {
        int t = (threadIdx.x >= (unsigned)off) ? sh[threadIdx.x - off] : 0;
        __syncthreads();
        sh[threadIdx.x] += t;
        __syncthreads();
    }
    if (i < n) g_rowptr[i + 1] = sh[threadIdx.x];
    if (threadIdx.x == 1023) g_blk[blockIdx.x] = sh[1023];
}

__global__ void scan_blocks(int nb) {
    if (threadIdx.x == 0 && blockIdx.x == 0) {
        int s = 0;
        for (int b = 0; b < nb; b++) { int t = g_blk[b]; g_blk[b] = s; s += t; }
        g_rowptr[0] = 0;
    }
}

__global__ void add_offsets(int n) {
    int i = blockIdx.x * 1024 + threadIdx.x;
    if (i < n) g_rowptr[i + 1] += g_blk[blockIdx.x];
}

__global__ void build_csr(int E, int N) {
    int e = blockIdx.x * blockDim.x + threadIdx.x;
    if (e < E) {
        int t = g_tgt[e];
        int s = g_src[e];
        if ((unsigned)t < (unsigned)N && (unsigned)s < (unsigned)N) {
            int pos = g_rowptr[t] + atomicAdd(&g_fill[t], 1);
            if ((unsigned)pos < (unsigned)MAX_EDGES) g_csr[pos] = s;
        }
    }
}

// ---------------------------------------------------------------------------
// fused weights, transposed to [o][k]; layer1 bf16 hi/lo, layer2 fp16 hi/lo
// ---------------------------------------------------------------------------
__global__ void fuse_weights_t(const float* __restrict__ w1, const float* __restrict__ c1,
                               const float* __restrict__ w2, const float* __restrict__ c2) {
    int idx = blockIdx.x * blockDim.x + threadIdx.x;
    const int T1 = 384 * 128;
    const int T2 = 384 * 64;
    if (idx < T1) {
        int k = idx >> 7, o = idx & 127;
        int i = k & 127, p = k >> 7;
        float v = 0.1f * c1[(i * 128 + o) * 3 + p];
        if (p == 0) v += w1[i * 128 + o];
        __nv_bfloat16 h = __float2bfloat16_rn(v);
        g_w1hi[o * 384 + k] = h;
        g_w1lo[o * 384 + k] = __float2bfloat16_rn(v - __bfloat162float(h));
    } else if (idx < T1 + T2) {
        int j = idx - T1;
        int k = j >> 6, o = j & 63;
        int i = k & 127, p = k >> 7;
        float v = 0.1f * c2[(i * 64 + o) * 3 + p];
        if (p == 0) v += w2[i * 64 + o];
        __half h = __float2half_rn(v);
        g_w2hi[o * 384 + k] = h;
        g_w2lo[o * 384 + k] = __float2half_rn(v - __half2float(h));
    }
}

// ---------------------------------------------------------------------------
// GEMM: Out[128-tile x BN] = Aug(X)[tile x 384] @ Weff + bias.
// BN==128 (layer1): bf16 A hi/lo + 3 MMAs (round-7 validated).
// BN==64  (layer2): fp16 A (exact), fp16 W hi/lo, 2 MMAs; A from g_a1h.
// BK=32, double-buffered SMEM (pad-8 16-bit rows), 8 warps = 4(M) x 2(N).
// Output stored fp16 for cheap downstream gathers.
// ---------------------------------------------------------------------------
template <int BN>
__global__ void __launch_bounds__(256) kan_gemm_mma(const float* __restrict__ Xp,
                                                    const float* __restrict__ bias, int N) {
    const int NT = BN / 16;                       // n8-tiles per warp
    const int NAt = (BN == 128) ? 2 : 1;          // A sub-tiles (hi[+lo])
    const uint32_t ASZ = 128 * 40 * 2;            // 16-bit tile, stride 40
    const uint32_t BSZ = (uint32_t)BN * 40 * 2;
    const uint32_t AHo = 0, BHo = NAt * ASZ;
    const uint32_t SBUF = NAt * ASZ + 2 * BSZ;

    extern __shared__ __align__(128) char smem[];
    uint32_t sb = smem_u32(smem);
    int tid = threadIdx.x, lane = tid & 31, wid = tid >> 5;
    int warp_m = wid & 3, warp_n = wid >> 2;
    int rowBase = blockIdx.x * 128;

    __half* Out = (BN == 128) ? g_h1h : g_h2h;

    // ---- producer indexing: thread -> (row, 16-col half) ----
    int rowl = tid >> 1, half = tid & 1;
    int nrow = rowBase + rowl;
    bool bact = rowl < BN;

    float4 xa[4];
    uint4 wh0, wh1, wl0, wl1;

    auto loadA = [&](int c) {
        int p = c >> 2;
        int i0 = (c & 3) * 32 + half * 16;
        if (nrow < N) {
            if (BN == 128) {
                const float4* ptr = (const float4*)Xp + (size_t)nrow * 32 + (i0 >> 2);
                xa[0] = ptr[0]; xa[1] = ptr[1]; xa[2] = ptr[2]; xa[3] = ptr[3];
            } else {
                const __half* A1 = g_a1h + (size_t)nrow * 128 + i0;
                uint4 u0 = *(const uint4*)A1;
                uint4 u1 = *(const uint4*)(A1 + 8);
                float2 f;
                f = __half22float2(*(__half2*)&u0.x); xa[0].x = f.x; xa[0].y = f.y;
                f = __half22float2(*(__half2*)&u0.y); xa[0].z = f.x; xa[0].w = f.y;
                f = __half22float2(*(__half2*)&u0.z); xa[1].x = f.x; xa[1].y = f.y;
                f = __half22float2(*(__half2*)&u0.w); xa[1].z = f.x; xa[1].w = f.y;
                f = __half22float2(*(__half2*)&u1.x); xa[2].x = f.x; xa[2].y = f.y;
                f = __half22float2(*(__half2*)&u1.y); xa[2].z = f.x; xa[2].w = f.y;
                f = __half22float2(*(__half2*)&u1.z); xa[3].x = f.x; xa[3].y = f.y;
                f = __half22float2(*(__half2*)&u1.w); xa[3].z = f.x; xa[3].w = f.y;
            }
        } else {
            xa[0] = xa[1] = xa[2] = xa[3] = make_float4(0.f, 0.f, 0.f, 0.f);
        }
        if (p == 1) {
#pragma unroll
            for (int j = 0; j < 4; j++) {
                xa[j].x *= xa[j].x; xa[j].y *= xa[j].y;
                xa[j].z *= xa[j].z; xa[j].w *= xa[j].w;
            }
        } else if (p == 2) {
#pragma unroll
            for (int j = 0; j < 4; j++) {
                xa[j].x = xa[j].x * xa[j].x * xa[j].x;
                xa[j].y = xa[j].y * xa[j].y * xa[j].y;
                xa[j].z = xa[j].z * xa[j].z * xa[j].z;
                xa[j].w = xa[j].w * xa[j].w * xa[j].w;
            }
        }
    };
    auto loadB = [&](int c) {
        if (!bact) return;
        size_t off = (size_t)rowl * 384 + c * 32 + half * 16;
        if (BN == 128) {
            wh0 = *(const uint4*)(g_w1hi + off); wh1 = *(const uint4*)(g_w1hi + off + 8);
            wl0 = *(const uint4*)(g_w1lo + off); wl1 = *(const uint4*)(g_w1lo + off + 8);
        } else {
            wh0 = *(const uint4*)(g_w2hi + off); wh1 = *(const uint4*)(g_w2hi + off + 8);
            wl0 = *(const uint4*)(g_w2lo + off); wl1 = *(const uint4*)(g_w2lo + off + 8);
        }
    };
    auto sts = [&](int buf) {
        char* abase = smem + buf * SBUF + AHo + rowl * 80 + half * 32;
        if (BN == 128) {
#pragma unroll
            for (int j = 0; j < 4; j++) {
                uint32_t h0, l0, h1, l1;
                split2(xa[j].x, xa[j].y, h0, l0);
                split2(xa[j].z, xa[j].w, h1, l1);
                *(uint2*)(abase + j * 8) = make_uint2(h0, h1);
                *(uint2*)(abase + ASZ + j * 8) = make_uint2(l0, l1);
            }
        } else {
#pragma unroll
            for (int j = 0; j < 4; j++) {
                *(uint2*)(abase + j * 8) =
                    make_uint2(pack2h(xa[j].x, xa[j].y), pack2h(xa[j].z, xa[j].w));
            }
        }
        if (bact) {
            char* bbase = smem + buf * SBUF + BHo + rowl * 80 + half * 32;
            *(uint4*)(bbase) = wh0;
            *(uint4*)(bbase + 16) = wh1;
            *(uint4*)(bbase + BSZ) = wl0;
            *(uint4*)(bbase + BSZ + 16) = wl1;
        }
    };

    // ---- consumer: ldmatrix lane offsets ----
    int lr = lane & 7, ls = lane >> 3;
    int a_row = lr + ((ls & 1) << 3);
    int a_k = (ls >> 1) << 3;
    int b_row = lr + ((ls >> 1) << 3);
    int b_k = (ls & 1) << 3;

    float acc[2][NT][4];
#pragma unroll
    for (int i = 0; i < 2; i++)
#pragma unroll
        for (int j = 0; j < NT; j++)
#pragma unroll
            for (int q = 0; q < 4; q++) acc[i][j][q] = 0.f;

    auto compute = [&](int buf) {
        uint32_t base = sb + buf * SBUF;
#pragma unroll
        for (int ks = 0; ks < 32; ks += 16) {
            uint32_t ah[2][4], al[2][4];
#pragma unroll
            for (int i = 0; i < 2; i++) {
                uint32_t ad = base + AHo + (uint32_t)(warp_m * 32 + i * 16 + a_row) * 80 +
                              (uint32_t)(ks + a_k) * 2;
                ldsm4(ah[i], ad);
                if (BN == 128) ldsm4(al[i], ad + ASZ);
            }
            uint32_t bh[NT][2], bl[NT][2];
#pragma unroll
            for (int j2 = 0; j2 < NT / 2; j2++) {
                uint32_t bd = base + BHo +
                              (uint32_t)(warp_n * (BN / 2) + j2 * 16 + b_row) * 80 +
                              (uint32_t)(ks + b_k) * 2;
                uint32_t t[4];
                ldsm4(t, bd);
                bh[2 * j2][0] = t[0]; bh[2 * j2][1] = t[1];
                bh[2 * j2 + 1][0] = t[2]; bh[2 * j2 + 1][1] = t[3];
                ldsm4(t, bd + BSZ);
                bl[2 * j2][0] = t[0]; bl[2 * j2][1] = t[1];
                bl[2 * j2 + 1][0] = t[2]; bl[2 * j2 + 1][1] = t[3];
            }
#pragma unroll
            for (int i = 0; i < 2; i++)
#pragma unroll
                for (int j = 0; j < NT; j++) {
                    if (BN == 128) {
                        mma16816(acc[i][j], ah[i], bh[j]);
                        mma16816(acc[i][j], ah[i], bl[j]);
                        mma16816(acc[i][j], al[i], bh[j]);
                    } else {
                        mma16816h(acc[i][j], ah[i], bh[j]);
                        mma16816h(acc[i][j], ah[i], bl[j]);
                    }
                }
        }
    };

    // ---- pipelined main loop over 12 K-chunks ----
    loadA(0); loadB(0);
    for (int c = 0; c < 12; c++) {
        int buf = c & 1;
        sts(buf);
        __syncthreads();
        if (c < 11) { loadA(c + 1); loadB(c + 1); }
        compute(buf);
        __syncthreads();
    }

    // ---- epilogue: bias (+relu), fp16 (__half2) stores ----
    int g = lane >> 2, t4 = lane & 3;
#pragma unroll
    for (int i = 0; i < 2; i++) {
        int m0 = rowBase + warp_m * 32 + i * 16 + g;
#pragma unroll
        for (int j = 0; j < NT; j++) {
            int col = warp_n * (BN / 2) + j * 8 + t4 * 2;
            float bx = bias[col], by = bias[col + 1];
            float v0 = acc[i][j][0] + bx, v1 = acc[i][j][1] + by;
            float v2 = acc[i][j][2] + bx, v3 = acc[i][j][3] + by;
            if (BN == 128) {
                v0 = fmaxf(v0, 0.f); v1 = fmaxf(v1, 0.f);
                v2 = fmaxf(v2, 0.f); v3 = fmaxf(v3, 0.f);
            }
            if (m0 < N)
                *(__half2*)(Out + (size_t)m0 * BN + col) = __floats2half2_rn(v0, v1);
            if (m0 + 8 < N)
                *(__half2*)(Out + (size_t)(m0 + 8) * BN + col) = __floats2half2_rn(v2, v3);
        }
    }
}

// ---------------------------------------------------------------------------
// gather-mean 1 (unroll-4, fp16 rows): a1[n][:] = mean_{s in nbrs(n)} h1[s][:]
// 32 lanes per node, each lane owns 4 halves (uint2 = 8B); row = 256B.
// Output written as fp16 (half2 pair).
// ---------------------------------------------------------------------------
__global__ void gather_mean1(int N) {
    int g = blockIdx.x * 8 + ((int)threadIdx.x >> 5);
    int lane = (int)threadIdx.x & 31;
    if (g >= N) return;
    const uint2* H = (const uint2*)g_h1h;   // 32 uint2 per row
    int beg = g_rowptr[g], end = g_rowptr[g + 1];
    float4 acc = make_float4(0.f, 0.f, 0.f, 0.f);
    int e = beg;
    for (; e + 4 <= end; e += 4) {
        int s0 = g_csr[e], s1 = g_csr[e + 1], s2 = g_csr[e + 2], s3 = g_csr[e + 3];
        uint2 v0 = H[(size_t)s0 * 32 + lane];
        uint2 v1 = H[(size_t)s1 * 32 + lane];
        uint2 v2 = H[(size_t)s2 * 32 + lane];
        uint2 v3 = H[(size_t)s3 * 32 + lane];
        accH(acc, v0); accH(acc, v1); accH(acc, v2); accH(acc, v3);
    }
    for (; e < end; e++) accH(acc, H[(size_t)g_csr[e] * 32 + lane]);
    float inv = 1.f / (float)max(end - beg, 1);
    acc.x *= inv; acc.y *= inv; acc.z *= inv; acc.w *= inv;
    ((uint2*)g_a1h)[(size_t)g * 32 + lane] =
        make_uint2(pack2h(acc.x, acc.y), pack2h(acc.z, acc.w));
}

// gather-mean 2 + log_softmax (fp16 rows); 16 lanes per node, row = 128B.
__global__ void gather_mean_lsm(float4* __restrict__ Out, int N) {
    int g = blockIdx.x * 16 + ((int)threadIdx.x >> 4);
    int lane = (int)threadIdx.x & 15;
    if (g >= N) return;
    const uint2* H = (const uint2*)g_h2h;   // 16 uint2 per row
    int beg = g_rowptr[g], end = g_rowptr[g + 1];
    float4 acc = make_float4(0.f, 0.f, 0.f, 0.f);
    int e = beg;
    for (; e + 4 <= end; e += 4) {
        int s0 = g_csr[e], s1 = g_csr[e + 1], s2 = g_csr[e + 2], s3 = g_csr[e + 3];
        uint2 v0 = H[(size_t)s0 * 16 + lane];
        uint2 v1 = H[(size_t)s1 * 16 + lane];
        uint2 v2 = H[(size_t)s2 * 16 + lane];
        uint2 v3 = H[(size_t)s3 * 16 + lane];
        accH(acc, v0); accH(acc, v1); accH(acc, v2); accH(acc, v3);
    }
    for (; e < end; e++) accH(acc, H[(size_t)g_csr[e] * 16 + lane]);
    float inv = 1.f / (float)max(end - beg, 1);
    acc.x *= inv; acc.y *= inv; acc.z *= inv; acc.w *= inv;

    float m = fmaxf(fmaxf(acc.x, acc.y), fmaxf(acc.z, acc.w));
#pragma unroll
    for (int off = 8; off; off >>= 1) m = fmaxf(m, __shfl_xor_sync(0xffffffffu, m, off));
    float s = __expf(acc.x - m) + __expf(acc.y - m) + __expf(acc.z - m) + __expf(acc.w - m);
#pragma unroll
    for (int off = 8; off; off >>= 1) s += __shfl_xor_sync(0xffffffffu, s, off);
    float lse = m + __logf(s);
    acc.x -= lse; acc.y -= lse; acc.z -= lse; acc.w -= lse;
    Out[(size_t)g * 16 + lane] = acc;
}

// ---------------------------------------------------------------------------
extern "C" void kernel_launch(void* const* d_in, const int* in_sizes, int n_in,
                              void* d_out, int out_size) {
    const float* x  = (const float*)d_in[0];
    const void*  ei = d_in[1];
    const float* w1 = (const float*)d_in[2];
    const float* b1 = (const float*)d_in[3];
    const float* c1 = (const float*)d_in[4];
    const float* w2 = (const float*)d_in[5];
    const float* b2 = (const float*)d_in[6];
    const float* c2 = (const float*)d_in[7];
    float4* out     = (float4*)d_out;

    int N = in_sizes[0] / 128;
    int E = in_sizes[1] / 2;

    const int SMEM1 = 2 * (2 * 10240 + 2 * 128 * 80);  // 81920
    const int SMEM2 = 2 * (1 * 10240 + 2 * 64 * 80);   // 40960
    cudaFuncSetAttribute((const void*)kan_gemm_mma<128>,
                         cudaFuncAttributeMaxDynamicSharedMemorySize, SMEM1);
    cudaFuncSetAttribute((const void*)kan_gemm_mma<64>,
                         cudaFuncAttributeMaxDynamicSharedMemorySize, SMEM2);

    // fork-join: CSR build on side stream, weights+GEMM1 on main (capture) stream.
    // Stream/events created per call and deliberately not destroyed (capture).
    cudaStream_t s1;
    cudaStreamCreateWithFlags(&s1, cudaStreamNonBlocking);
    cudaEvent_t evF, evJ;
    cudaEventCreateWithFlags(&evF, cudaEventDisableTiming);
    cudaEventCreateWithFlags(&evJ, cudaEventDisableTiming);

    cudaEventRecord(evF, 0);
    cudaStreamWaitEvent(s1, evF, 0);

    // ---- side stream: CSR chain ----
    zero_int2<<<(N + 255) / 256, 256, 0, s1>>>(N);
    detect_dtype<<<1, 32, 0, s1>>>((const int*)ei);
    convert_hist<<<(E + 255) / 256, 256, 0, s1>>>(ei, E, N);
    int nb = (N + 1023) / 1024;
    scan_partials<<<nb, 1024, 0, s1>>>(N);
    scan_blocks<<<1, 32, 0, s1>>>(nb);
    add_offsets<<<nb, 1024, 0, s1>>>(N);
    build_csr<<<(E + 255) / 256, 256, 0, s1>>>(E, N);
    cudaEventRecord(evJ, s1);

    // ---- main stream: weights + GEMM1 (overlapped with CSR) ----
    fuse_weights_t<<<(384 * 128 + 384 * 64 + 255) / 256, 256>>>(w1, c1, w2, c2);
    int tiles = (N + 127) / 128;
    kan_gemm_mma<128><<<tiles, 256, SMEM1>>>(x, b1, N);

    // join: gathers need both CSR and h1
    cudaStreamWaitEvent(0, evJ, 0);

    // aggregate 1 (mean)
    gather_mean1<<<(N + 7) / 8, 256>>>(N);

    // layer 2
    kan_gemm_mma<64><<<tiles, 256, SMEM2>>>(nullptr, b2, N);

    // aggregate 2 (mean) + log_softmax, straight into d_out
    gather_mean_lsm<<<(N + 15) / 16, 256>>>(out, N);
}

// round 12
// speedup vs baseline: 1.6318x; 1.3751x over previous
#include <cuda_runtime.h>
#include <cuda_bf16.h>
#include <cuda_fp16.h>
#include <math.h>
#include <stdint.h>

// ---------------------------------------------------------------------------
// KAN_GNN: both GEMMs on pure-fp16 mma.sync (single MMA; fp32 accumulate) --
// empirically the fp16 message quantization already bounds accuracy, so the
// hi/lo split bought nothing. Messages h1/h2 and a1 stored fp16. CSR pull
// aggregation, fused mean+log_softmax; CSR build overlapped with GEMM1.
// kan(x,w,b,c) == [x,x^2,x^3] @ W_eff + b,
//   W_eff[p*128+i][o] = (p==0 ? w[i][o] : 0) + 0.1*c[i][o][p]
// ---------------------------------------------------------------------------

#define MAX_NODES 100000
#define MAX_EDGES 1600000

__device__ __half g_w1h[128 * 384];          // W1_eff^T fp16, [o][k]
__device__ __half g_w2h[64 * 384];           // W2_eff^T fp16, [o][k]
__device__ __half g_h1h[(size_t)MAX_NODES * 128];  // fp16 messages, layer 1
__device__ __half g_h2h[(size_t)MAX_NODES * 64];   // fp16 messages, layer 2
__device__ __half g_a1h[(size_t)MAX_NODES * 128];  // fp16 aggregated features
__device__ int    g_src[MAX_EDGES];
__device__ int    g_tgt[MAX_EDGES];
__device__ int    g_is64;
__device__ int    g_cnt[MAX_NODES];
__device__ int    g_fill[MAX_NODES];
__device__ int    g_rowptr[MAX_NODES + 1];
__device__ int    g_csr[MAX_EDGES];
__device__ int    g_blk[128];

// ---------------------------------------------------------------------------
// helpers
// ---------------------------------------------------------------------------
__device__ __forceinline__ uint32_t smem_u32(const void* p) {
    uint32_t a;
    asm("{ .reg .u64 t; cvta.to.shared.u64 t, %1; cvt.u32.u64 %0, t; }" : "=r"(a) : "l"(p));
    return a;
}
__device__ __forceinline__ void ldsm4(uint32_t r[4], uint32_t addr) {
    asm volatile("ldmatrix.sync.aligned.m8n8.x4.shared.b16 {%0,%1,%2,%3}, [%4];"
                 : "=r"(r[0]), "=r"(r[1]), "=r"(r[2]), "=r"(r[3]) : "r"(addr));
}
__device__ __forceinline__ void mma16816h(float d[4], const uint32_t a[4], const uint32_t b[2]) {
    asm volatile(
        "mma.sync.aligned.m16n8k16.row.col.f32.f16.f16.f32 "
        "{%0,%1,%2,%3}, {%4,%5,%6,%7}, {%8,%9}, {%0,%1,%2,%3};"
        : "+f"(d[0]), "+f"(d[1]), "+f"(d[2]), "+f"(d[3])
        : "r"(a[0]), "r"(a[1]), "r"(a[2]), "r"(a[3]), "r"(b[0]), "r"(b[1]));
}
__device__ __forceinline__ uint32_t pack2h(float x, float y) {
    __half2 h = __floats2half2_rn(x, y);
    return *(uint32_t*)&h;
}
// accumulate 4 halves (uint2) into float4
__device__ __forceinline__ void accH(float4& a, uint2 v) {
    __half2 h0 = *(__half2*)&v.x, h1 = *(__half2*)&v.y;
    float2 f0 = __half22float2(h0), f1 = __half22float2(h1);
    a.x += f0.x; a.y += f0.y; a.z += f1.x; a.w += f1.y;
}

// ---------------------------------------------------------------------------
// Edge dtype detection + fused convert/histogram
// ---------------------------------------------------------------------------
__global__ void detect_dtype(const int* __restrict__ buf) {
    if (threadIdx.x == 0 && blockIdx.x == 0) {
        int any = 0;
        for (int i = 1; i < 256; i += 2) any |= buf[i];
        g_is64 = (any == 0) ? 1 : 0;
    }
}

__global__ void zero_int2(int N) {
    int i = blockIdx.x * blockDim.x + threadIdx.x;
    if (i < N) { g_cnt[i] = 0; g_fill[i] = 0; }
}

__global__ void convert_hist(const void* __restrict__ ei, int E, int N) {
    int e = blockIdx.x * blockDim.x + threadIdx.x;
    if (e >= E) return;
    int s, t;
    if (g_is64) {
        const long long* p = (const long long*)ei;
        s = (int)p[e]; t = (int)p[e + E];
    } else {
        const int* p = (const int*)ei;
        s = p[e]; t = p[e + E];
    }
    g_src[e] = s;
    g_tgt[e] = t;
    if ((unsigned)t < (unsigned)N) atomicAdd(&g_cnt[t], 1);
}

// ---------------------------------------------------------------------------
// multi-block scan: rowptr[i+1] = sum cnt[0..i]
// ---------------------------------------------------------------------------
__global__ void scan_partials(int n) {
    __shared__ int sh[1024];
    int i = blockIdx.x * 1024 + threadIdx.x;
    sh[threadIdx.x] = (i < n) ? g_cnt[i] : 0;
    __syncthreads();
    for (int off = 1; off < 1024; off <<= 1) {
        int t = (threadIdx.x >= (unsigned)off) ? sh[threadIdx.x - off] : 0;
        __syncthreads();
        sh[threadIdx.x] += t;
        __syncthreads();
    }
    if (i < n) g_rowptr[i + 1] = sh[threadIdx.x];
    if (threadIdx.x == 1023) g_blk[blockIdx.x] = sh[1023];
}

__global__ void scan_blocks(int nb) {
    if (threadIdx.x == 0 && blockIdx.x == 0) {
        int s = 0;
        for (int b = 0; b < nb; b++) { int t = g_blk[b]; g_blk[b] = s; s += t; }
        g_rowptr[0] = 0;
    }
}

__global__ void add_offsets(int n) {
    int i = blockIdx.x * 1024 + threadIdx.x;
    if (i < n) g_rowptr[i + 1] += g_blk[blockIdx.x];
}

__global__ void build_csr(int E, int N) {
    int e = blockIdx.x * blockDim.x + threadIdx.x;
    if (e < E) {
        int t = g_tgt[e];
        int s = g_src[e];
        if ((unsigned)t < (unsigned)N && (unsigned)s < (unsigned)N) {
            int pos = g_rowptr[t] + atomicAdd(&g_fill[t], 1);
            if ((unsigned)pos < (unsigned)MAX_EDGES) g_csr[pos] = s;
        }
    }
}

// ---------------------------------------------------------------------------
// fused weights, transposed to [o][k], fp16
// ---------------------------------------------------------------------------
__global__ void fuse_weights_t(const float* __restrict__ w1, const float* __restrict__ c1,
                               const float* __restrict__ w2, const float* __restrict__ c2) {
    int idx = blockIdx.x * blockDim.x + threadIdx.x;
    const int T1 = 384 * 128;
    const int T2 = 384 * 64;
    if (idx < T1) {
        int k = idx >> 7, o = idx & 127;
        int i = k & 127, p = k >> 7;
        float v = 0.1f * c1[(i * 128 + o) * 3 + p];
        if (p == 0) v += w1[i * 128 + o];
        g_w1h[o * 384 + k] = __float2half_rn(v);
    } else if (idx < T1 + T2) {
        int j = idx - T1;
        int k = j >> 6, o = j & 63;
        int i = k & 127, p = k >> 7;
        float v = 0.1f * c2[(i * 64 + o) * 3 + p];
        if (p == 0) v += w2[i * 64 + o];
        g_w2h[o * 384 + k] = __float2half_rn(v);
    }
}

// ---------------------------------------------------------------------------
// fp16 GEMM: Out[128-tile x BN] = Aug(X)[tile x 384] @ Weff + bias.
// Single fp16 MMA per tile (fp32 accumulate). BK=32, double-buffered SMEM
// (pad-8 16-bit rows), 8 warps = 4(M) x 2(N). Output stored fp16.
// BN==128: X = fp32 input x (powers computed fp32, packed fp16).
// BN==64:  X = g_a1h (fp16 aggregated features).
// ---------------------------------------------------------------------------
template <int BN>
__global__ void __launch_bounds__(256) kan_gemm_mma(const float* __restrict__ Xp,
                                                    const float* __restrict__ bias, int N) {
    const int NT = BN / 16;                       // n8-tiles per warp
    const uint32_t ASZ = 128 * 40 * 2;            // fp16 tile, stride 40 halves
    const uint32_t BSZ = (uint32_t)BN * 40 * 2;
    const uint32_t AHo = 0, BHo = ASZ;
    const uint32_t SBUF = ASZ + BSZ;

    extern __shared__ __align__(128) char smem[];
    uint32_t sb = smem_u32(smem);
    int tid = threadIdx.x, lane = tid & 31, wid = tid >> 5;
    int warp_m = wid & 3, warp_n = wid >> 2;
    int rowBase = blockIdx.x * 128;

    __half* Out = (BN == 128) ? g_h1h : g_h2h;

    // ---- producer indexing: thread -> (row, 16-col half) ----
    int rowl = tid >> 1, half = tid & 1;
    int nrow = rowBase + rowl;
    bool bact = rowl < BN;

    float4 xa[4];
    uint4 wh0, wh1;

    auto loadA = [&](int c) {
        int p = c >> 2;
        int i0 = (c & 3) * 32 + half * 16;
        if (nrow < N) {
            if (BN == 128) {
                const float4* ptr = (const float4*)Xp + (size_t)nrow * 32 + (i0 >> 2);
                xa[0] = ptr[0]; xa[1] = ptr[1]; xa[2] = ptr[2]; xa[3] = ptr[3];
            } else {
                const __half* A1 = g_a1h + (size_t)nrow * 128 + i0;
                uint4 u0 = *(const uint4*)A1;
                uint4 u1 = *(const uint4*)(A1 + 8);
                float2 f;
                f = __half22float2(*(__half2*)&u0.x); xa[0].x = f.x; xa[0].y = f.y;
                f = __half22float2(*(__half2*)&u0.y); xa[0].z = f.x; xa[0].w = f.y;
                f = __half22float2(*(__half2*)&u0.z); xa[1].x = f.x; xa[1].y = f.y;
                f = __half22float2(*(__half2*)&u0.w); xa[1].z = f.x; xa[1].w = f.y;
                f = __half22float2(*(__half2*)&u1.x); xa[2].x = f.x; xa[2].y = f.y;
                f = __half22float2(*(__half2*)&u1.y); xa[2].z = f.x; xa[2].w = f.y;
                f = __half22float2(*(__half2*)&u1.z); xa[3].x = f.x; xa[3].y = f.y;
                f = __half22float2(*(__half2*)&u1.w); xa[3].z = f.x; xa[3].w = f.y;
            }
        } else {
            xa[0] = xa[1] = xa[2] = xa[3] = make_float4(0.f, 0.f, 0.f, 0.f);
        }
        if (p == 1) {
#pragma unroll
            for (int j = 0; j < 4; j++) {
                xa[j].x *= xa[j].x; xa[j].y *= xa[j].y;
                xa[j].z *= xa[j].z; xa[j].w *= xa[j].w;
            }
        } else if (p == 2) {
#pragma unroll
            for (int j = 0; j < 4; j++) {
                xa[j].x = xa[j].x * xa[j].x * xa[j].x;
                xa[j].y = xa[j].y * xa[j].y * xa[j].y;
                xa[j].z = xa[j].z * xa[j].z * xa[j].z;
                xa[j].w = xa[j].w * xa[j].w * xa[j].w;
            }
        }
    };
    auto loadB = [&](int c) {
        if (!bact) return;
        size_t off = (size_t)rowl * 384 + c * 32 + half * 16;
        const __half* W = (BN == 128) ? g_w1h : g_w2h;
        wh0 = *(const uint4*)(W + off);
        wh1 = *(const uint4*)(W + off + 8);
    };
    auto sts = [&](int buf) {
        char* abase = smem + buf * SBUF + AHo + rowl * 80 + half * 32;
#pragma unroll
        for (int j = 0; j < 4; j++) {
            *(uint2*)(abase + j * 8) =
                make_uint2(pack2h(xa[j].x, xa[j].y), pack2h(xa[j].z, xa[j].w));
        }
        if (bact) {
            char* bbase = smem + buf * SBUF + BHo + rowl * 80 + half * 32;
            *(uint4*)(bbase) = wh0;
            *(uint4*)(bbase + 16) = wh1;
        }
    };

    // ---- consumer: ldmatrix lane offsets ----
    int lr = lane & 7, ls = lane >> 3;
    int a_row = lr + ((ls & 1) << 3);
    int a_k = (ls >> 1) << 3;
    int b_row = lr + ((ls >> 1) << 3);
    int b_k = (ls & 1) << 3;

    float acc[2][NT][4];
#pragma unroll
    for (int i = 0; i < 2; i++)
#pragma unroll
        for (int j = 0; j < NT; j++)
#pragma unroll
            for (int q = 0; q < 4; q++) acc[i][j][q] = 0.f;

    auto compute = [&](int buf) {
        uint32_t base = sb + buf * SBUF;
#pragma unroll
        for (int ks = 0; ks < 32; ks += 16) {
            uint32_t ah[2][4];
#pragma unroll
            for (int i = 0; i < 2; i++) {
                uint32_t ad = base + AHo + (uint32_t)(warp_m * 32 + i * 16 + a_row) * 80 +
                              (uint32_t)(ks + a_k) * 2;
                ldsm4(ah[i], ad);
            }
            uint32_t bh[NT][2];
#pragma unroll
            for (int j2 = 0; j2 < NT / 2; j2++) {
                uint32_t bd = base + BHo +
                              (uint32_t)(warp_n * (BN / 2) + j2 * 16 + b_row) * 80 +
                              (uint32_t)(ks + b_k) * 2;
                uint32_t t[4];
                ldsm4(t, bd);
                bh[2 * j2][0] = t[0]; bh[2 * j2][1] = t[1];
                bh[2 * j2 + 1][0] = t[2]; bh[2 * j2 + 1][1] = t[3];
            }
#pragma unroll
            for (int i = 0; i < 2; i++)
#pragma unroll
                for (int j = 0; j < NT; j++)
                    mma16816h(acc[i][j], ah[i], bh[j]);
        }
    };

    // ---- pipelined main loop over 12 K-chunks ----
    loadA(0); loadB(0);
    for (int c = 0; c < 12; c++) {
        int buf = c & 1;
        sts(buf);
        __syncthreads();
        if (c < 11) { loadA(c + 1); loadB(c + 1); }
        compute(buf);
        __syncthreads();
    }

    // ---- epilogue: bias (+relu), fp16 (__half2) stores ----
    int g = lane >> 2, t4 = lane & 3;
#pragma unroll
    for (int i = 0; i < 2; i++) {
        int m0 = rowBase + warp_m * 32 + i * 16 + g;
#pragma unroll
        for (int j = 0; j < NT; j++) {
            int col = warp_n * (BN / 2) + j * 8 + t4 * 2;
            float bx = bias[col], by = bias[col + 1];
            float v0 = acc[i][j][0] + bx, v1 = acc[i][j][1] + by;
            float v2 = acc[i][j][2] + bx, v3 = acc[i][j][3] + by;
            if (BN == 128) {
                v0 = fmaxf(v0, 0.f); v1 = fmaxf(v1, 0.f);
                v2 = fmaxf(v2, 0.f); v3 = fmaxf(v3, 0.f);
            }
            if (m0 < N)
                *(__half2*)(Out + (size_t)m0 * BN + col) = __floats2half2_rn(v0, v1);
            if (m0 + 8 < N)
                *(__half2*)(Out + (size_t)(m0 + 8) * BN + col) = __floats2half2_rn(v2, v3);
        }
    }
}

// ---------------------------------------------------------------------------
// gather-mean 1 (unroll-4, fp16 rows): a1[n][:] = mean_{s in nbrs(n)} h1[s][:]
// 32 lanes per node, each lane owns 4 halves (uint2 = 8B); row = 256B.
// ---------------------------------------------------------------------------
__global__ void gather_mean1(int N) {
    int g = blockIdx.x * 8 + ((int)threadIdx.x >> 5);
    int lane = (int)threadIdx.x & 31;
    if (g >= N) return;
    const uint2* H = (const uint2*)g_h1h;   // 32 uint2 per row
    int beg = g_rowptr[g], end = g_rowptr[g + 1];
    float4 acc = make_float4(0.f, 0.f, 0.f, 0.f);
    int e = beg;
    for (; e + 4 <= end; e += 4) {
        int s0 = g_csr[e], s1 = g_csr[e + 1], s2 = g_csr[e + 2], s3 = g_csr[e + 3];
        uint2 v0 = H[(size_t)s0 * 32 + lane];
        uint2 v1 = H[(size_t)s1 * 32 + lane];
        uint2 v2 = H[(size_t)s2 * 32 + lane];
        uint2 v3 = H[(size_t)s3 * 32 + lane];
        accH(acc, v0); accH(acc, v1); accH(acc, v2); accH(acc, v3);
    }
    for (; e < end; e++) accH(acc, H[(size_t)g_csr[e] * 32 + lane]);
    float inv = 1.f / (float)max(end - beg, 1);
    acc.x *= inv; acc.y *= inv; acc.z *= inv; acc.w *= inv;
    ((uint2*)g_a1h)[(size_t)g * 32 + lane] =
        make_uint2(pack2h(acc.x, acc.y), pack2h(acc.z, acc.w));
}

// gather-mean 2 + log_softmax (fp16 rows); 16 lanes per node, row = 128B.
__global__ void gather_mean_lsm(float4* __restrict__ Out, int N) {
    int g = blockIdx.x * 16 + ((int)threadIdx.x >> 4);
    int lane = (int)threadIdx.x & 15;
    if (g >= N) return;
    const uint2* H = (const uint2*)g_h2h;   // 16 uint2 per row
    int beg = g_rowptr[g], end = g_rowptr[g + 1];
    float4 acc = make_float4(0.f, 0.f, 0.f, 0.f);
    int e = beg;
    for (; e + 4 <= end; e += 4) {
        int s0 = g_csr[e], s1 = g_csr[e + 1], s2 = g_csr[e + 2], s3 = g_csr[e + 3];
        uint2 v0 = H[(size_t)s0 * 16 + lane];
        uint2 v1 = H[(size_t)s1 * 16 + lane];
        uint2 v2 = H[(size_t)s2 * 16 + lane];
        uint2 v3 = H[(size_t)s3 * 16 + lane];
        accH(acc, v0); accH(acc, v1); accH(acc, v2); accH(acc, v3);
    }
    for (; e < end; e++) accH(acc, H[(size_t)g_csr[e] * 16 + lane]);
    float inv = 1.f / (float)max(end - beg, 1);
    acc.x *= inv; acc.y *= inv; acc.z *= inv; acc.w *= inv;

    float m = fmaxf(fmaxf(acc.x, acc.y), fmaxf(acc.z, acc.w));
#pragma unroll
    for (int off = 8; off; off >>= 1) m = fmaxf(m, __shfl_xor_sync(0xffffffffu, m, off));
    float s = __expf(acc.x - m) + __expf(acc.y - m) + __expf(acc.z - m) + __expf(acc.w - m);
#pragma unroll
    for (int off = 8; off; off >>= 1) s += __shfl_xor_sync(0xffffffffu, s, off);
    float lse = m + __logf(s);
    acc.x -= lse; acc.y -= lse; acc.z -= lse; acc.w -= lse;
    Out[(size_t)g * 16 + lane] = acc;
}

// ---------------------------------------------------------------------------
extern "C" void kernel_launch(void* const* d_in, const int* in_sizes, int n_in,
                              void* d_out, int out_size) {
    const float* x  = (const float*)d_in[0];
    const void*  ei = d_in[1];
    const float* w1 = (const float*)d_in[2];
    const float* b1 = (const float*)d_in[3];
    const float* c1 = (const float*)d_in[4];
    const float* w2 = (const float*)d_in[5];
    const float* b2 = (const float*)d_in[6];
    const float* c2 = (const float*)d_in[7];
    float4* out     = (float4*)d_out;

    int N = in_sizes[0] / 128;
    int E = in_sizes[1] / 2;

    const int SMEM1 = 2 * (10240 + 128 * 80);  // 40960
    const int SMEM2 = 2 * (10240 + 64 * 80);   // 30720
    cudaFuncSetAttribute((const void*)kan_gemm_mma<128>,
                         cudaFuncAttributeMaxDynamicSharedMemorySize, SMEM1);
    cudaFuncSetAttribute((const void*)kan_gemm_mma<64>,
                         cudaFuncAttributeMaxDynamicSharedMemorySize, SMEM2);

    // fork-join: CSR build on side stream, weights+GEMM1 on main (capture) stream.
    // Stream/events created per call and deliberately not destroyed (capture).
    cudaStream_t s1;
    cudaStreamCreateWithFlags(&s1, cudaStreamNonBlocking);
    cudaEvent_t evF, evJ;
    cudaEventCreateWithFlags(&evF, cudaEventDisableTiming);
    cudaEventCreateWithFlags(&evJ, cudaEventDisableTiming);

    cudaEventRecord(evF, 0);
    cudaStreamWaitEvent(s1, evF, 0);

    // ---- side stream: CSR chain ----
    zero_int2<<<(N + 255) / 256, 256, 0, s1>>>(N);
    detect_dtype<<<1, 32, 0, s1>>>((const int*)ei);
    convert_hist<<<(E + 255) / 256, 256, 0, s1>>>(ei, E, N);
    int nb = (N + 1023) / 1024;
    scan_partials<<<nb, 1024, 0, s1>>>(N);
    scan_blocks<<<1, 32, 0, s1>>>(nb);
    add_offsets<<<nb, 1024, 0, s1>>>(N);
    build_csr<<<(E + 255) / 256, 256, 0, s1>>>(E, N);
    cudaEventRecord(evJ, s1);

    // ---- main stream: weights + GEMM1 (overlapped with CSR) ----
    fuse_weights_t<<<(384 * 128 + 384 * 64 + 255) / 256, 256>>>(w1, c1, w2, c2);
    int tiles = (N + 127) / 128;
    kan_gemm_mma<128><<<tiles, 256, SMEM1>>>(x, b1, N);

    // join: gathers need both CSR and h1
    cudaStreamWaitEvent(0, evJ, 0);

    // aggregate 1 (mean)
    gather_mean1<<<(N + 7) / 8, 256>>>(N);

    // layer 2
    kan_gemm_mma<64><<<tiles, 256, SMEM2>>>(nullptr, b2, N);

    // aggregate 2 (mean) + log_softmax, straight into d_out
    gather_mean_lsm<<<(N + 15) / 16, 256>>>(out, N);
}

// round 13
// speedup vs baseline: 1.7689x; 1.0840x over previous
#include <cuda_runtime.h>
#include <cuda_bf16.h>
#include <cuda_fp16.h>
#include <math.h>
#include <stdint.h>

// ---------------------------------------------------------------------------
// KAN_GNN: both GEMMs pure-fp16 mma.sync (single MMA, fp32 accumulate);
// messages h1/h2/a1 stored fp16. CSR pull aggregation with 16B-per-lane
// gathers (latency-bound -> maximize independent chains per warp).
// CSR build decodes edge_index directly (no src/tgt materialization),
// overlapped with GEMM1 on a side stream.
// kan(x,w,b,c) == [x,x^2,x^3] @ W_eff + b,
//   W_eff[p*128+i][o] = (p==0 ? w[i][o] : 0) + 0.1*c[i][o][p]
// ---------------------------------------------------------------------------

#define MAX_NODES 100000
#define MAX_EDGES 1600000

__device__ __align__(256) __half g_w1h[128 * 384];  // W1_eff^T fp16, [o][k]
__device__ __align__(256) __half g_w2h[64 * 384];   // W2_eff^T fp16, [o][k]
__device__ __align__(256) __half g_h1h[(size_t)MAX_NODES * 128];
__device__ __align__(256) __half g_h2h[(size_t)MAX_NODES * 64];
__device__ __align__(256) __half g_a1h[(size_t)MAX_NODES * 128];
__device__ int    g_is64;
__device__ int    g_cnt[MAX_NODES];
__device__ int    g_fill[MAX_NODES];
__device__ int    g_rowptr[MAX_NODES + 1];
__device__ int    g_csr[MAX_EDGES];
__device__ int    g_blk[128];

// ---------------------------------------------------------------------------
// helpers
// ---------------------------------------------------------------------------
__device__ __forceinline__ uint32_t smem_u32(const void* p) {
    uint32_t a;
    asm("{ .reg .u64 t; cvta.to.shared.u64 t, %1; cvt.u32.u64 %0, t; }" : "=r"(a) : "l"(p));
    return a;
}
__device__ __forceinline__ void ldsm4(uint32_t r[4], uint32_t addr) {
    asm volatile("ldmatrix.sync.aligned.m8n8.x4.shared.b16 {%0,%1,%2,%3}, [%4];"
                 : "=r"(r[0]), "=r"(r[1]), "=r"(r[2]), "=r"(r[3]) : "r"(addr));
}
__device__ __forceinline__ void mma16816h(float d[4], const uint32_t a[4], const uint32_t b[2]) {
    asm volatile(
        "mma.sync.aligned.m16n8k16.row.col.f32.f16.f16.f32 "
        "{%0,%1,%2,%3}, {%4,%5,%6,%7}, {%8,%9}, {%0,%1,%2,%3};"
        : "+f"(d[0]), "+f"(d[1]), "+f"(d[2]), "+f"(d[3])
        : "r"(a[0]), "r"(a[1]), "r"(a[2]), "r"(a[3]), "r"(b[0]), "r"(b[1]));
}
__device__ __forceinline__ uint32_t pack2h(float x, float y) {
    __half2 h = __floats2half2_rn(x, y);
    return *(uint32_t*)&h;
}
// accumulate 8 halves (uint4) into two float4
__device__ __forceinline__ void accH8(float4& a0, float4& a1, uint4 v) {
    float2 f;
    f = __half22float2(*(__half2*)&v.x); a0.x += f.x; a0.y += f.y;
    f = __half22float2(*(__half2*)&v.y); a0.z += f.x; a0.w += f.y;
    f = __half22float2(*(__half2*)&v.z); a1.x += f.x; a1.y += f.y;
    f = __half22float2(*(__half2*)&v.w); a1.z += f.x; a1.w += f.y;
}
// decode edge endpoint from raw edge_index buffer
__device__ __forceinline__ int edge_at(const void* ei, long idx, int is64) {
    return is64 ? (int)((const long long*)ei)[idx] : ((const int*)ei)[idx];
}

// ---------------------------------------------------------------------------
// Edge dtype detection + histogram (decodes edge_index directly)
// ---------------------------------------------------------------------------
__global__ void detect_dtype(const int* __restrict__ buf) {
    if (threadIdx.x == 0 && blockIdx.x == 0) {
        int any = 0;
        for (int i = 1; i < 256; i += 2) any |= buf[i];
        g_is64 = (any == 0) ? 1 : 0;
    }
}

__global__ void zero_int2(int N) {
    int i = blockIdx.x * blockDim.x + threadIdx.x;
    if (i < N) { g_cnt[i] = 0; g_fill[i] = 0; }
}

__global__ void hist_kernel(const void* __restrict__ ei, int E, int N) {
    int e = blockIdx.x * blockDim.x + threadIdx.x;
    if (e >= E) return;
    int t = edge_at(ei, (long)e + E, g_is64);
    if ((unsigned)t < (unsigned)N) atomicAdd(&g_cnt[t], 1);
}

// ---------------------------------------------------------------------------
// multi-block scan: rowptr[i+1] = sum cnt[0..i]
// ---------------------------------------------------------------------------
__global__ void scan_partials(int n) {
    __shared__ int sh[1024];
    int i = blockIdx.x * 1024 + threadIdx.x;
    sh[threadIdx.x] = (i < n) ? g_cnt[i] : 0;
    __syncthreads();
    for (int off = 1; off < 1024; off <<= 1) {
        int t = (threadIdx.x >= (unsigned)off) ? sh[threadIdx.x - off] : 0;
        __syncthreads();
        sh[threadIdx.x] += t;
        __syncthreads();
    }
    if (i < n) g_rowptr[i + 1] = sh[threadIdx.x];
    if (threadIdx.x == 1023) g_blk[blockIdx.x] = sh[1023];
}

__global__ void scan_blocks(int nb) {
    if (threadIdx.x == 0 && blockIdx.x == 0) {
        int s = 0;
        for (int b = 0; b < nb; b++) { int t = g_blk[b]; g_blk[b] = s; s += t; }
        g_rowptr[0] = 0;
    }
}

__global__ void add_offsets(int n) {
    int i = blockIdx.x * 1024 + threadIdx.x;
    if (i < n) g_rowptr[i + 1] += g_blk[blockIdx.x];
}

__global__ void build_csr(const void* __restrict__ ei, int E, int N) {
    int e = blockIdx.x * blockDim.x + threadIdx.x;
    if (e < E) {
        int t = edge_at(ei, (long)e + E, g_is64);
        int s = edge_at(ei, e, g_is64);
        if ((unsigned)t < (unsigned)N && (unsigned)s < (unsigned)N) {
            int pos = g_rowptr[t] + atomicAdd(&g_fill[t], 1);
            if ((unsigned)pos < (unsigned)MAX_EDGES) g_csr[pos] = s;
        }
    }
}

// ---------------------------------------------------------------------------
// fused weights, transposed to [o][k], fp16
// ---------------------------------------------------------------------------
__global__ void fuse_weights_t(const float* __restrict__ w1, const float* __restrict__ c1,
                               const float* __restrict__ w2, const float* __restrict__ c2) {
    int idx = blockIdx.x * blockDim.x + threadIdx.x;
    const int T1 = 384 * 128;
    const int T2 = 384 * 64;
    if (idx < T1) {
        int k = idx >> 7, o = idx & 127;
        int i = k & 127, p = k >> 7;
        float v = 0.1f * c1[(i * 128 + o) * 3 + p];
        if (p == 0) v += w1[i * 128 + o];
        g_w1h[o * 384 + k] = __float2half_rn(v);
    } else if (idx < T1 + T2) {
        int j = idx - T1;
        int k = j >> 6, o = j & 63;
        int i = k & 127, p = k >> 7;
        float v = 0.1f * c2[(i * 64 + o) * 3 + p];
        if (p == 0) v += w2[i * 64 + o];
        g_w2h[o * 384 + k] = __float2half_rn(v);
    }
}

// ---------------------------------------------------------------------------
// fp16 GEMM: Out[128-tile x BN] = Aug(X)[tile x 384] @ Weff + bias.
// Single fp16 MMA per tile (fp32 accumulate). BK=32, double-buffered SMEM
// (pad-8 16-bit rows), 8 warps = 4(M) x 2(N). Output stored fp16.
// ---------------------------------------------------------------------------
template <int BN>
__global__ void __launch_bounds__(256) kan_gemm_mma(const float* __restrict__ Xp,
                                                    const float* __restrict__ bias, int N) {
    const int NT = BN / 16;                       // n8-tiles per warp
    const uint32_t ASZ = 128 * 40 * 2;            // fp16 tile, stride 40 halves
    const uint32_t BSZ = (uint32_t)BN * 40 * 2;
    const uint32_t AHo = 0, BHo = ASZ;
    const uint32_t SBUF = ASZ + BSZ;

    extern __shared__ __align__(128) char smem[];
    uint32_t sb = smem_u32(smem);
    int tid = threadIdx.x, lane = tid & 31, wid = tid >> 5;
    int warp_m = wid & 3, warp_n = wid >> 2;
    int rowBase = blockIdx.x * 128;

    __half* Out = (BN == 128) ? g_h1h : g_h2h;

    // ---- producer indexing: thread -> (row, 16-col half) ----
    int rowl = tid >> 1, half = tid & 1;
    int nrow = rowBase + rowl;
    bool bact = rowl < BN;

    float4 xa[4];
    uint4 wh0, wh1;

    auto loadA = [&](int c) {
        int p = c >> 2;
        int i0 = (c & 3) * 32 + half * 16;
        if (nrow < N) {
            if (BN == 128) {
                const float4* ptr = (const float4*)Xp + (size_t)nrow * 32 + (i0 >> 2);
                xa[0] = ptr[0]; xa[1] = ptr[1]; xa[2] = ptr[2]; xa[3] = ptr[3];
            } else {
                const __half* A1 = g_a1h + (size_t)nrow * 128 + i0;
                uint4 u0 = *(const uint4*)A1;
                uint4 u1 = *(const uint4*)(A1 + 8);
                float2 f;
                f = __half22float2(*(__half2*)&u0.x); xa[0].x = f.x; xa[0].y = f.y;
                f = __half22float2(*(__half2*)&u0.y); xa[0].z = f.x; xa[0].w = f.y;
                f = __half22float2(*(__half2*)&u0.z); xa[1].x = f.x; xa[1].y = f.y;
                f = __half22float2(*(__half2*)&u0.w); xa[1].z = f.x; xa[1].w = f.y;
                f = __half22float2(*(__half2*)&u1.x); xa[2].x = f.x; xa[2].y = f.y;
                f = __half22float2(*(__half2*)&u1.y); xa[2].z = f.x; xa[2].w = f.y;
                f = __half22float2(*(__half2*)&u1.z); xa[3].x = f.x; xa[3].y = f.y;
                f = __half22float2(*(__half2*)&u1.w); xa[3].z = f.x; xa[3].w = f.y;
            }
        } else {
            xa[0] = xa[1] = xa[2] = xa[3] = make_float4(0.f, 0.f, 0.f, 0.f);
        }
        if (p == 1) {
#pragma unroll
            for (int j = 0; j < 4; j++) {
                xa[j].x *= xa[j].x; xa[j].y *= xa[j].y;
                xa[j].z *= xa[j].z; xa[j].w *= xa[j].w;
            }
        } else if (p == 2) {
#pragma unroll
            for (int j = 0; j < 4; j++) {
                xa[j].x = xa[j].x * xa[j].x * xa[j].x;
                xa[j].y = xa[j].y * xa[j].y * xa[j].y;
                xa[j].z = xa[j].z * xa[j].z * xa[j].z;
                xa[j].w = xa[j].w * xa[j].w * xa[j].w;
            }
        }
    };
    auto loadB = [&](int c) {
        if (!bact) return;
        size_t off = (size_t)rowl * 384 + c * 32 + half * 16;
        const __half* W = (BN == 128) ? g_w1h : g_w2h;
        wh0 = *(const uint4*)(W + off);
        wh1 = *(const uint4*)(W + off + 8);
    };
    auto sts = [&](int buf) {
        char* abase = smem + buf * SBUF + AHo + rowl * 80 + half * 32;
#pragma unroll
        for (int j = 0; j < 4; j++) {
            *(uint2*)(abase + j * 8) =
                make_uint2(pack2h(xa[j].x, xa[j].y), pack2h(xa[j].z, xa[j].w));
        }
        if (bact) {
            char* bbase = smem + buf * SBUF + BHo + rowl * 80 + half * 32;
            *(uint4*)(bbase) = wh0;
            *(uint4*)(bbase + 16) = wh1;
        }
    };

    // ---- consumer: ldmatrix lane offsets ----
    int lr = lane & 7, ls = lane >> 3;
    int a_row = lr + ((ls & 1) << 3);
    int a_k = (ls >> 1) << 3;
    int b_row = lr + ((ls >> 1) << 3);
    int b_k = (ls & 1) << 3;

    float acc[2][NT][4];
#pragma unroll
    for (int i = 0; i < 2; i++)
#pragma unroll
        for (int j = 0; j < NT; j++)
#pragma unroll
            for (int q = 0; q < 4; q++) acc[i][j][q] = 0.f;

    auto compute = [&](int buf) {
        uint32_t base = sb + buf * SBUF;
#pragma unroll
        for (int ks = 0; ks < 32; ks += 16) {
            uint32_t ah[2][4];
#pragma unroll
            for (int i = 0; i < 2; i++) {
                uint32_t ad = base + AHo + (uint32_t)(warp_m * 32 + i * 16 + a_row) * 80 +
                              (uint32_t)(ks + a_k) * 2;
                ldsm4(ah[i], ad);
            }
            uint32_t bh[NT][2];
#pragma unroll
            for (int j2 = 0; j2 < NT / 2; j2++) {
                uint32_t bd = base + BHo +
                              (uint32_t)(warp_n * (BN / 2) + j2 * 16 + b_row) * 80 +
                              (uint32_t)(ks + b_k) * 2;
                uint32_t t[4];
                ldsm4(t, bd);
                bh[2 * j2][0] = t[0]; bh[2 * j2][1] = t[1];
                bh[2 * j2 + 1][0] = t[2]; bh[2 * j2 + 1][1] = t[3];
            }
#pragma unroll
            for (int i = 0; i < 2; i++)
#pragma unroll
                for (int j = 0; j < NT; j++)
                    mma16816h(acc[i][j], ah[i], bh[j]);
        }
    };

    // ---- pipelined main loop over 12 K-chunks ----
    loadA(0); loadB(0);
    for (int c = 0; c < 12; c++) {
        int buf = c & 1;
        sts(buf);
        __syncthreads();
        if (c < 11) { loadA(c + 1); loadB(c + 1); }
        compute(buf);
        __syncthreads();
    }

    // ---- epilogue: bias (+relu), fp16 (__half2) stores ----
    int g = lane >> 2, t4 = lane & 3;
#pragma unroll
    for (int i = 0; i < 2; i++) {
        int m0 = rowBase + warp_m * 32 + i * 16 + g;
#pragma unroll
        for (int j = 0; j < NT; j++) {
            int col = warp_n * (BN / 2) + j * 8 + t4 * 2;
            float bx = bias[col], by = bias[col + 1];
            float v0 = acc[i][j][0] + bx, v1 = acc[i][j][1] + by;
            float v2 = acc[i][j][2] + bx, v3 = acc[i][j][3] + by;
            if (BN == 128) {
                v0 = fmaxf(v0, 0.f); v1 = fmaxf(v1, 0.f);
                v2 = fmaxf(v2, 0.f); v3 = fmaxf(v3, 0.f);
            }
            if (m0 < N)
                *(__half2*)(Out + (size_t)m0 * BN + col) = __floats2half2_rn(v0, v1);
            if (m0 + 8 < N)
                *(__half2*)(Out + (size_t)(m0 + 8) * BN + col) = __floats2half2_rn(v2, v3);
        }
    }
}

// ---------------------------------------------------------------------------
// gather-mean 1 (unroll-4, 16B lanes): a1[n][:] = mean_{s in nbrs(n)} h1[s][:]
// 16 lanes per node, each lane owns one uint4 (8 halves); row = 256B.
// 16 nodes per 256-thread block.
// ---------------------------------------------------------------------------
__global__ void gather_mean1(int N) {
    int g = blockIdx.x * 16 + ((int)threadIdx.x >> 4);
    int lane = (int)threadIdx.x & 15;
    if (g >= N) return;
    const uint4* H = (const uint4*)g_h1h;   // 16 uint4 per row
    int beg = g_rowptr[g], end = g_rowptr[g + 1];
    float4 a0 = make_float4(0.f, 0.f, 0.f, 0.f);
    float4 a1 = make_float4(0.f, 0.f, 0.f, 0.f);
    int e = beg;
    for (; e + 4 <= end; e += 4) {
        int s0 = g_csr[e], s1 = g_csr[e + 1], s2 = g_csr[e + 2], s3 = g_csr[e + 3];
        uint4 v0 = H[(size_t)s0 * 16 + lane];
        uint4 v1 = H[(size_t)s1 * 16 + lane];
        uint4 v2 = H[(size_t)s2 * 16 + lane];
        uint4 v3 = H[(size_t)s3 * 16 + lane];
        accH8(a0, a1, v0); accH8(a0, a1, v1); accH8(a0, a1, v2); accH8(a0, a1, v3);
    }
    for (; e < end; e++) accH8(a0, a1, H[(size_t)g_csr[e] * 16 + lane]);
    float inv = 1.f / (float)max(end - beg, 1);
    a0.x *= inv; a0.y *= inv; a0.z *= inv; a0.w *= inv;
    a1.x *= inv; a1.y *= inv; a1.z *= inv; a1.w *= inv;
    uint4 w;
    w.x = pack2h(a0.x, a0.y); w.y = pack2h(a0.z, a0.w);
    w.z = pack2h(a1.x, a1.y); w.w = pack2h(a1.z, a1.w);
    ((uint4*)g_a1h)[(size_t)g * 16 + lane] = w;
}

// gather-mean 2 + log_softmax; 8 lanes per node, lane owns uint4 (8 halves);
// row = 128B. 32 nodes per 256-thread block.
__global__ void gather_mean_lsm(float4* __restrict__ Out, int N) {
    int g = blockIdx.x * 32 + ((int)threadIdx.x >> 3);
    int lane = (int)threadIdx.x & 7;
    if (g >= N) return;
    const uint4* H = (const uint4*)g_h2h;   // 8 uint4 per row
    int beg = g_rowptr[g], end = g_rowptr[g + 1];
    float4 a0 = make_float4(0.f, 0.f, 0.f, 0.f);
    float4 a1 = make_float4(0.f, 0.f, 0.f, 0.f);
    int e = beg;
    for (; e + 4 <= end; e += 4) {
        int s0 = g_csr[e], s1 = g_csr[e + 1], s2 = g_csr[e + 2], s3 = g_csr[e + 3];
        uint4 v0 = H[(size_t)s0 * 8 + lane];
        uint4 v1 = H[(size_t)s1 * 8 + lane];
        uint4 v2 = H[(size_t)s2 * 8 + lane];
        uint4 v3 = H[(size_t)s3 * 8 + lane];
        accH8(a0, a1, v0); accH8(a0, a1, v1); accH8(a0, a1, v2); accH8(a0, a1, v3);
    }
    for (; e < end; e++) accH8(a0, a1, H[(size_t)g_csr[e] * 8 + lane]);
    float inv = 1.f / (float)max(end - beg, 1);
    a0.x *= inv; a0.y *= inv; a0.z *= inv; a0.w *= inv;
    a1.x *= inv; a1.y *= inv; a1.z *= inv; a1.w *= inv;

    // log_softmax over the 8-lane group (64 values)
    float m = fmaxf(fmaxf(fmaxf(a0.x, a0.y), fmaxf(a0.z, a0.w)),
                    fmaxf(fmaxf(a1.x, a1.y), fmaxf(a1.z, a1.w)));
#pragma unroll
    for (int off = 4; off; off >>= 1) m = fmaxf(m, __shfl_xor_sync(0xffffffffu, m, off));
    float s = __expf(a0.x - m) + __expf(a0.y - m) + __expf(a0.z - m) + __expf(a0.w - m) +
              __expf(a1.x - m) + __expf(a1.y - m) + __expf(a1.z - m) + __expf(a1.w - m);
#pragma unroll
    for (int off = 4; off; off >>= 1) s += __shfl_xor_sync(0xffffffffu, s, off);
    float lse = m + __logf(s);
    a0.x -= lse; a0.y -= lse; a0.z -= lse; a0.w -= lse;
    a1.x -= lse; a1.y -= lse; a1.z -= lse; a1.w -= lse;
    Out[(size_t)g * 16 + lane * 2] = a0;
    Out[(size_t)g * 16 + lane * 2 + 1] = a1;
}

// ---------------------------------------------------------------------------
extern "C" void kernel_launch(void* const* d_in, const int* in_sizes, int n_in,
                              void* d_out, int out_size) {
    const float* x  = (const float*)d_in[0];
    const void*  ei = d_in[1];
    const float* w1 = (const float*)d_in[2];
    const float* b1 = (const float*)d_in[3];
    const float* c1 = (const float*)d_in[4];
    const float* w2 = (const float*)d_in[5];
    const float* b2 = (const float*)d_in[6];
    const float* c2 = (const float*)d_in[7];
    float4* out     = (float4*)d_out;

    int N = in_sizes[0] / 128;
    int E = in_sizes[1] / 2;

    const int SMEM1 = 2 * (10240 + 128 * 80);  // 40960
    const int SMEM2 = 2 * (10240 + 64 * 80);   // 30720
    cudaFuncSetAttribute((const void*)kan_gemm_mma<128>,
                         cudaFuncAttributeMaxDynamicSharedMemorySize, SMEM1);
    cudaFuncSetAttribute((const void*)kan_gemm_mma<64>,
                         cudaFuncAttributeMaxDynamicSharedMemorySize, SMEM2);

    // fork-join: CSR build on side stream, weights+GEMM1 on main (capture) stream.
    // Stream/events created per call and deliberately not destroyed (capture).
    cudaStream_t s1;
    cudaStreamCreateWithFlags(&s1, cudaStreamNonBlocking);
    cudaEvent_t evF, evJ;
    cudaEventCreateWithFlags(&evF, cudaEventDisableTiming);
    cudaEventCreateWithFlags(&evJ, cudaEventDisableTiming);

    cudaEventRecord(evF, 0);
    cudaStreamWaitEvent(s1, evF, 0);

    // ---- side stream: CSR chain (decodes edge_index in place) ----
    zero_int2<<<(N + 255) / 256, 256, 0, s1>>>(N);
    detect_dtype<<<1, 32, 0, s1>>>((const int*)ei);
    hist_kernel<<<(E + 255) / 256, 256, 0, s1>>>(ei, E, N);
    int nb = (N + 1023) / 1024;
    scan_partials<<<nb, 1024, 0, s1>>>(N);
    scan_blocks<<<1, 32, 0, s1>>>(nb);
    add_offsets<<<nb, 1024, 0, s1>>>(N);
    build_csr<<<(E + 255) / 256, 256, 0, s1>>>(ei, E, N);
    cudaEventRecord(evJ, s1);

    // ---- main stream: weights + GEMM1 (overlapped with CSR) ----
    fuse_weights_t<<<(384 * 128 + 384 * 64 + 255) / 256, 256>>>(w1, c1, w2, c2);
    int tiles = (N + 127) / 128;
    kan_gemm_mma<128><<<tiles, 256, SMEM1>>>(x, b1, N);

    // join: gathers need both CSR and h1
    cudaStreamWaitEvent(0, evJ, 0);

    // aggregate 1 (mean)
    gather_mean1<<<(N + 15) / 16, 256>>>(N);

    // layer 2
    kan_gemm_mma<64><<<tiles, 256, SMEM2>>>(nullptr, b2, N);

    // aggregate 2 (mean) + log_softmax, straight into d_out
    gather_mean_lsm<<<(N + 31) / 32, 256>>>(out, N);
}

// round 14
// speedup vs baseline: 1.7704x; 1.0008x over previous
#include <cuda_runtime.h>
#include <cuda_bf16.h>
#include <cuda_fp16.h>
#include <math.h>
#include <stdint.h>

// ---------------------------------------------------------------------------
// KAN_GNN: both GEMMs pure-fp16 mma.sync (single MMA, fp32 accumulate);
// messages h1/h2/a1 stored fp16. CSR pull aggregation with 16B-per-lane
// unroll-8 gathers. CSR build decodes edge_index directly with 4-edge
// vectorized loads; overlapped with GEMM1 on a side stream.
// kan(x,w,b,c) == [x,x^2,x^3] @ W_eff + b,
//   W_eff[p*128+i][o] = (p==0 ? w[i][o] : 0) + 0.1*c[i][o][p]
// ---------------------------------------------------------------------------

#define MAX_NODES 100000
#define MAX_EDGES 1600000

__device__ __align__(256) __half g_w1h[128 * 384];  // W1_eff^T fp16, [o][k]
__device__ __align__(256) __half g_w2h[64 * 384];   // W2_eff^T fp16, [o][k]
__device__ __align__(256) __half g_h1h[(size_t)MAX_NODES * 128];
__device__ __align__(256) __half g_h2h[(size_t)MAX_NODES * 64];
__device__ __align__(256) __half g_a1h[(size_t)MAX_NODES * 128];
__device__ int    g_is64;
__device__ int    g_cnt[MAX_NODES];
__device__ int    g_fill[MAX_NODES];
__device__ int    g_rowptr[MAX_NODES + 1];
__device__ int    g_csr[MAX_EDGES];
__device__ int    g_blk[128];

// ---------------------------------------------------------------------------
// helpers
// ---------------------------------------------------------------------------
__device__ __forceinline__ uint32_t smem_u32(const void* p) {
    uint32_t a;
    asm("{ .reg .u64 t; cvta.to.shared.u64 t, %1; cvt.u32.u64 %0, t; }" : "=r"(a) : "l"(p));
    return a;
}
__device__ __forceinline__ void ldsm4(uint32_t r[4], uint32_t addr) {
    asm volatile("ldmatrix.sync.aligned.m8n8.x4.shared.b16 {%0,%1,%2,%3}, [%4];"
                 : "=r"(r[0]), "=r"(r[1]), "=r"(r[2]), "=r"(r[3]) : "r"(addr));
}
__device__ __forceinline__ void mma16816h(float d[4], const uint32_t a[4], const uint32_t b[2]) {
    asm volatile(
        "mma.sync.aligned.m16n8k16.row.col.f32.f16.f16.f32 "
        "{%0,%1,%2,%3}, {%4,%5,%6,%7}, {%8,%9}, {%0,%1,%2,%3};"
        : "+f"(d[0]), "+f"(d[1]), "+f"(d[2]), "+f"(d[3])
        : "r"(a[0]), "r"(a[1]), "r"(a[2]), "r"(a[3]), "r"(b[0]), "r"(b[1]));
}
__device__ __forceinline__ uint32_t pack2h(float x, float y) {
    __half2 h = __floats2half2_rn(x, y);
    return *(uint32_t*)&h;
}
// accumulate 8 halves (uint4) into two float4
__device__ __forceinline__ void accH8(float4& a0, float4& a1, uint4 v) {
    float2 f;
    f = __half22float2(*(__half2*)&v.x); a0.x += f.x; a0.y += f.y;
    f = __half22float2(*(__half2*)&v.y); a0.z += f.x; a0.w += f.y;
    f = __half22float2(*(__half2*)&v.z); a1.x += f.x; a1.y += f.y;
    f = __half22float2(*(__half2*)&v.w); a1.z += f.x; a1.w += f.y;
}
// decode edge endpoint from raw edge_index buffer
__device__ __forceinline__ int edge_at(const void* ei, long idx, int is64) {
    return is64 ? (int)((const long long*)ei)[idx] : ((const int*)ei)[idx];
}
// load 4 consecutive edge endpoints starting at base index (base % 4 == 0)
__device__ __forceinline__ void edge4(const void* ei, long base, int is64, int v[4]) {
    if (is64) {
        longlong2 p0 = ((const longlong2*)ei)[base >> 1];
        longlong2 p1 = ((const longlong2*)ei)[(base >> 1) + 1];
        v[0] = (int)p0.x; v[1] = (int)p0.y; v[2] = (int)p1.x; v[3] = (int)p1.y;
    } else {
        int4 p = ((const int4*)ei)[base >> 2];
        v[0] = p.x; v[1] = p.y; v[2] = p.z; v[3] = p.w;
    }
}

// ---------------------------------------------------------------------------
// Edge dtype detection + histogram (4 edges / thread)
// ---------------------------------------------------------------------------
__global__ void detect_dtype(const int* __restrict__ buf) {
    if (threadIdx.x == 0 && blockIdx.x == 0) {
        int any = 0;
        for (int i = 1; i < 256; i += 2) any |= buf[i];
        g_is64 = (any == 0) ? 1 : 0;
    }
}

__global__ void zero_int2(int N) {
    int i = blockIdx.x * blockDim.x + threadIdx.x;
    if (i < N) { g_cnt[i] = 0; g_fill[i] = 0; }
}

__global__ void hist_kernel(const void* __restrict__ ei, int E, int N) {
    int q = blockIdx.x * blockDim.x + threadIdx.x;   // quad index
    int e0 = q * 4;
    if (e0 >= E) return;
    int is64 = g_is64;
    if (e0 + 4 <= E) {
        int t[4];
        edge4(ei, (long)E + e0, is64, t);
#pragma unroll
        for (int j = 0; j < 4; j++)
            if ((unsigned)t[j] < (unsigned)N) atomicAdd(&g_cnt[t[j]], 1);
    } else {
        for (int e = e0; e < E; e++) {
            int t = edge_at(ei, (long)E + e, is64);
            if ((unsigned)t < (unsigned)N) atomicAdd(&g_cnt[t], 1);
        }
    }
}

// ---------------------------------------------------------------------------
// multi-block scan: rowptr[i+1] = sum cnt[0..i]
// ---------------------------------------------------------------------------
__global__ void scan_partials(int n) {
    __shared__ int sh[1024];
    int i = blockIdx.x * 1024 + threadIdx.x;
    sh[threadIdx.x] = (i < n) ? g_cnt[i] : 0;
    __syncthreads();
    for (int off = 1; off < 1024; off <<= 1) {
        int t = (threadIdx.x >= (unsigned)off) ? sh[threadIdx.x - off] : 0;
        __syncthreads();
        sh[threadIdx.x] += t;
        __syncthreads();
    }
    if (i < n) g_rowptr[i + 1] = sh[threadIdx.x];
    if (threadIdx.x == 1023) g_blk[blockIdx.x] = sh[1023];
}

// add block-prefix offsets; each block sums g_blk[0..bid) itself (<=98 ints)
__global__ void add_offsets(int n) {
    __shared__ int off_s;
    if (threadIdx.x == 0) {
        int s = 0;
        for (int b = 0; b < (int)blockIdx.x; b++) s += g_blk[b];
        off_s = s;
        if (blockIdx.x == 0) g_rowptr[0] = 0;
    }
    __syncthreads();
    int i = blockIdx.x * 1024 + threadIdx.x;
    if (i < n) g_rowptr[i + 1] += off_s;
}

__global__ void build_csr(const void* __restrict__ ei, int E, int N) {
    int q = blockIdx.x * blockDim.x + threadIdx.x;
    int e0 = q * 4;
    if (e0 >= E) return;
    int is64 = g_is64;
    if (e0 + 4 <= E) {
        int t[4], s[4];
        edge4(ei, (long)E + e0, is64, t);
        edge4(ei, e0, is64, s);
#pragma unroll
        for (int j = 0; j < 4; j++) {
            if ((unsigned)t[j] < (unsigned)N && (unsigned)s[j] < (unsigned)N) {
                int pos = g_rowptr[t[j]] + atomicAdd(&g_fill[t[j]], 1);
                if ((unsigned)pos < (unsigned)MAX_EDGES) g_csr[pos] = s[j];
            }
        }
    } else {
        for (int e = e0; e < E; e++) {
            int t = edge_at(ei, (long)E + e, is64);
            int s = edge_at(ei, e, is64);
            if ((unsigned)t < (unsigned)N && (unsigned)s < (unsigned)N) {
                int pos = g_rowptr[t] + atomicAdd(&g_fill[t], 1);
                if ((unsigned)pos < (unsigned)MAX_EDGES) g_csr[pos] = s;
            }
        }
    }
}

// ---------------------------------------------------------------------------
// fused weights, transposed to [o][k], fp16
// ---------------------------------------------------------------------------
__global__ void fuse_weights_t(const float* __restrict__ w1, const float* __restrict__ c1,
                               const float* __restrict__ w2, const float* __restrict__ c2) {
    int idx = blockIdx.x * blockDim.x + threadIdx.x;
    const int T1 = 384 * 128;
    const int T2 = 384 * 64;
    if (idx < T1) {
        int k = idx >> 7, o = idx & 127;
        int i = k & 127, p = k >> 7;
        float v = 0.1f * c1[(i * 128 + o) * 3 + p];
        if (p == 0) v += w1[i * 128 + o];
        g_w1h[o * 384 + k] = __float2half_rn(v);
    } else if (idx < T1 + T2) {
        int j = idx - T1;
        int k = j >> 6, o = j & 63;
        int i = k & 127, p = k >> 7;
        float v = 0.1f * c2[(i * 64 + o) * 3 + p];
        if (p == 0) v += w2[i * 64 + o];
        g_w2h[o * 384 + k] = __float2half_rn(v);
    }
}

// ---------------------------------------------------------------------------
// fp16 GEMM: Out[128-tile x BN] = Aug(X)[tile x 384] @ Weff + bias.
// Single fp16 MMA per tile (fp32 accumulate). BK=32, double-buffered SMEM
// (pad-8 16-bit rows), 8 warps = 4(M) x 2(N). Output stored fp16.
// ---------------------------------------------------------------------------
template <int BN>
__global__ void __launch_bounds__(256) kan_gemm_mma(const float* __restrict__ Xp,
                                                    const float* __restrict__ bias, int N) {
    const int NT = BN / 16;                       // n8-tiles per warp
    const uint32_t ASZ = 128 * 40 * 2;            // fp16 tile, stride 40 halves
    const uint32_t BSZ = (uint32_t)BN * 40 * 2;
    const uint32_t AHo = 0, BHo = ASZ;
    const uint32_t SBUF = ASZ + BSZ;

    extern __shared__ __align__(128) char smem[];
    uint32_t sb = smem_u32(smem);
    int tid = threadIdx.x, lane = tid & 31, wid = tid >> 5;
    int warp_m = wid & 3, warp_n = wid >> 2;
    int rowBase = blockIdx.x * 128;

    __half* Out = (BN == 128) ? g_h1h : g_h2h;

    // ---- producer indexing: thread -> (row, 16-col half) ----
    int rowl = tid >> 1, half = tid & 1;
    int nrow = rowBase + rowl;
    bool bact = rowl < BN;

    float4 xa[4];
    uint4 wh0, wh1;

    auto loadA = [&](int c) {
        int p = c >> 2;
        int i0 = (c & 3) * 32 + half * 16;
        if (nrow < N) {
            if (BN == 128) {
                const float4* ptr = (const float4*)Xp + (size_t)nrow * 32 + (i0 >> 2);
                xa[0] = ptr[0]; xa[1] = ptr[1]; xa[2] = ptr[2]; xa[3] = ptr[3];
            } else {
                const __half* A1 = g_a1h + (size_t)nrow * 128 + i0;
                uint4 u0 = *(const uint4*)A1;
                uint4 u1 = *(const uint4*)(A1 + 8);
                float2 f;
                f = __half22float2(*(__half2*)&u0.x); xa[0].x = f.x; xa[0].y = f.y;
                f = __half22float2(*(__half2*)&u0.y); xa[0].z = f.x; xa[0].w = f.y;
                f = __half22float2(*(__half2*)&u0.z); xa[1].x = f.x; xa[1].y = f.y;
                f = __half22float2(*(__half2*)&u0.w); xa[1].z = f.x; xa[1].w = f.y;
                f = __half22float2(*(__half2*)&u1.x); xa[2].x = f.x; xa[2].y = f.y;
                f = __half22float2(*(__half2*)&u1.y); xa[2].z = f.x; xa[2].w = f.y;
                f = __half22float2(*(__half2*)&u1.z); xa[3].x = f.x; xa[3].y = f.y;
                f = __half22float2(*(__half2*)&u1.w); xa[3].z = f.x; xa[3].w = f.y;
            }
        } else {
            xa[0] = xa[1] = xa[2] = xa[3] = make_float4(0.f, 0.f, 0.f, 0.f);
        }
        if (p == 1) {
#pragma unroll
            for (int j = 0; j < 4; j++) {
                xa[j].x *= xa[j].x; xa[j].y *= xa[j].y;
                xa[j].z *= xa[j].z; xa[j].w *= xa[j].w;
            }
        } else if (p == 2) {
#pragma unroll
            for (int j = 0; j < 4; j++) {
                xa[j].x = xa[j].x * xa[j].x * xa[j].x;
                xa[j].y = xa[j].y * xa[j].y * xa[j].y;
                xa[j].z = xa[j].z * xa[j].z * xa[j].z;
                xa[j].w = xa[j].w * xa[j].w * xa[j].w;
            }
        }
    };
    auto loadB = [&](int c) {
        if (!bact) return;
        size_t off = (size_t)rowl * 384 + c * 32 + half * 16;
        const __half* W = (BN == 128) ? g_w1h : g_w2h;
        wh0 = *(const uint4*)(W + off);
        wh1 = *(const uint4*)(W + off + 8);
    };
    auto sts = [&](int buf) {
        char* abase = smem + buf * SBUF + AHo + rowl * 80 + half * 32;
#pragma unroll
        for (int j = 0; j < 4; j++) {
            *(uint2*)(abase + j * 8) =
                make_uint2(pack2h(xa[j].x, xa[j].y), pack2h(xa[j].z, xa[j].w));
        }
        if (bact) {
            char* bbase = smem + buf * SBUF + BHo + rowl * 80 + half * 32;
            *(uint4*)(bbase) = wh0;
            *(uint4*)(bbase + 16) = wh1;
        }
    };

    // ---- consumer: ldmatrix lane offsets ----
    int lr = lane & 7, ls = lane >> 3;
    int a_row = lr + ((ls & 1) << 3);
    int a_k = (ls >> 1) << 3;
    int b_row = lr + ((ls >> 1) << 3);
    int b_k = (ls & 1) << 3;

    float acc[2][NT][4];
#pragma unroll
    for (int i = 0; i < 2; i++)
#pragma unroll
        for (int j = 0; j < NT; j++)
#pragma unroll
            for (int q = 0; q < 4; q++) acc[i][j][q] = 0.f;

    auto compute = [&](int buf) {
        uint32_t base = sb + buf * SBUF;
#pragma unroll
        for (int ks = 0; ks < 32; ks += 16) {
            uint32_t ah[2][4];
#pragma unroll
            for (int i = 0; i < 2; i++) {
                uint32_t ad = base + AHo + (uint32_t)(warp_m * 32 + i * 16 + a_row) * 80 +
                              (uint32_t)(ks + a_k) * 2;
                ldsm4(ah[i], ad);
            }
            uint32_t bh[NT][2];
#pragma unroll
            for (int j2 = 0; j2 < NT / 2; j2++) {
                uint32_t bd = base + BHo +
                              (uint32_t)(warp_n * (BN / 2) + j2 * 16 + b_row) * 80 +
                              (uint32_t)(ks + b_k) * 2;
                uint32_t t[4];
                ldsm4(t, bd);
                bh[2 * j2][0] = t[0]; bh[2 * j2][1] = t[1];
                bh[2 * j2 + 1][0] = t[2]; bh[2 * j2 + 1][1] = t[3];
            }
#pragma unroll
            for (int i = 0; i < 2; i++)
#pragma unroll
                for (int j = 0; j < NT; j++)
                    mma16816h(acc[i][j], ah[i], bh[j]);
        }
    };

    // ---- pipelined main loop over 12 K-chunks ----
    loadA(0); loadB(0);
    for (int c = 0; c < 12; c++) {
        int buf = c & 1;
        sts(buf);
        __syncthreads();
        if (c < 11) { loadA(c + 1); loadB(c + 1); }
        compute(buf);
        __syncthreads();
    }

    // ---- epilogue: bias (+relu), fp16 (__half2) stores ----
    int g = lane >> 2, t4 = lane & 3;
#pragma unroll
    for (int i = 0; i < 2; i++) {
        int m0 = rowBase + warp_m * 32 + i * 16 + g;
#pragma unroll
        for (int j = 0; j < NT; j++) {
            int col = warp_n * (BN / 2) + j * 8 + t4 * 2;
            float bx = bias[col], by = bias[col + 1];
            float v0 = acc[i][j][0] + bx, v1 = acc[i][j][1] + by;
            float v2 = acc[i][j][2] + bx, v3 = acc[i][j][3] + by;
            if (BN == 128) {
                v0 = fmaxf(v0, 0.f); v1 = fmaxf(v1, 0.f);
                v2 = fmaxf(v2, 0.f); v3 = fmaxf(v3, 0.f);
            }
            if (m0 < N)
                *(__half2*)(Out + (size_t)m0 * BN + col) = __floats2half2_rn(v0, v1);
            if (m0 + 8 < N)
                *(__half2*)(Out + (size_t)(m0 + 8) * BN + col) = __floats2half2_rn(v2, v3);
        }
    }
}

// ---------------------------------------------------------------------------
// gather-mean 1 (unroll-8, 16B lanes): a1[n][:] = mean_{s in nbrs(n)} h1[s][:]
// 16 lanes per node, each lane owns one uint4 (8 halves); row = 256B.
// ---------------------------------------------------------------------------
__global__ void gather_mean1(int N) {
    int g = blockIdx.x * 16 + ((int)threadIdx.x >> 4);
    int lane = (int)threadIdx.x & 15;
    if (g >= N) return;
    const uint4* H = (const uint4*)g_h1h;   // 16 uint4 per row
    int beg = g_rowptr[g], end = g_rowptr[g + 1];
    float4 a0 = make_float4(0.f, 0.f, 0.f, 0.f);
    float4 a1 = make_float4(0.f, 0.f, 0.f, 0.f);
    int e = beg;
    for (; e + 8 <= end; e += 8) {
        int s[8];
#pragma unroll
        for (int j = 0; j < 8; j++) s[j] = g_csr[e + j];
        uint4 v[8];
#pragma unroll
        for (int j = 0; j < 8; j++) v[j] = H[(size_t)s[j] * 16 + lane];
#pragma unroll
        for (int j = 0; j < 8; j++) accH8(a0, a1, v[j]);
    }
    for (; e + 4 <= end; e += 4) {
        int s0 = g_csr[e], s1 = g_csr[e + 1], s2 = g_csr[e + 2], s3 = g_csr[e + 3];
        uint4 v0 = H[(size_t)s0 * 16 + lane];
        uint4 v1 = H[(size_t)s1 * 16 + lane];
        uint4 v2 = H[(size_t)s2 * 16 + lane];
        uint4 v3 = H[(size_t)s3 * 16 + lane];
        accH8(a0, a1, v0); accH8(a0, a1, v1); accH8(a0, a1, v2); accH8(a0, a1, v3);
    }
    for (; e < end; e++) accH8(a0, a1, H[(size_t)g_csr[e] * 16 + lane]);
    float inv = 1.f / (float)max(end - beg, 1);
    a0.x *= inv; a0.y *= inv; a0.z *= inv; a0.w *= inv;
    a1.x *= inv; a1.y *= inv; a1.z *= inv; a1.w *= inv;
    uint4 w;
    w.x = pack2h(a0.x, a0.y); w.y = pack2h(a0.z, a0.w);
    w.z = pack2h(a1.x, a1.y); w.w = pack2h(a1.z, a1.w);
    ((uint4*)g_a1h)[(size_t)g * 16 + lane] = w;
}

// gather-mean 2 + log_softmax (unroll-8); 8 lanes per node, uint4 per lane.
__global__ void gather_mean_lsm(float4* __restrict__ Out, int N) {
    int g = blockIdx.x * 32 + ((int)threadIdx.x >> 3);
    int lane = (int)threadIdx.x & 7;
    if (g >= N) return;
    const uint4* H = (const uint4*)g_h2h;   // 8 uint4 per row
    int beg = g_rowptr[g], end = g_rowptr[g + 1];
    float4 a0 = make_float4(0.f, 0.f, 0.f, 0.f);
    float4 a1 = make_float4(0.f, 0.f, 0.f, 0.f);
    int e = beg;
    for (; e + 8 <= end; e += 8) {
        int s[8];
#pragma unroll
        for (int j = 0; j < 8; j++) s[j] = g_csr[e + j];
        uint4 v[8];
#pragma unroll
        for (int j = 0; j < 8; j++) v[j] = H[(size_t)s[j] * 8 + lane];
#pragma unroll
        for (int j = 0; j < 8; j++) accH8(a0, a1, v[j]);
    }
    for (; e + 4 <= end; e += 4) {
        int s0 = g_csr[e], s1 = g_csr[e + 1], s2 = g_csr[e + 2], s3 = g_csr[e + 3];
        uint4 v0 = H[(size_t)s0 * 8 + lane];
        uint4 v1 = H[(size_t)s1 * 8 + lane];
        uint4 v2 = H[(size_t)s2 * 8 + lane];
        uint4 v3 = H[(size_t)s3 * 8 + lane];
        accH8(a0, a1, v0); accH8(a0, a1, v1); accH8(a0, a1, v2); accH8(a0, a1, v3);
    }
    for (; e < end; e++) accH8(a0, a1, H[(size_t)g_csr[e] * 8 + lane]);
    float inv = 1.f / (float)max(end - beg, 1);
    a0.x *= inv; a0.y *= inv; a0.z *= inv; a0.w *= inv;
    a1.x *= inv; a1.y *= inv; a1.z *= inv; a1.w *= inv;

    // log_softmax over the 8-lane group (64 values)
    float m = fmaxf(fmaxf(fmaxf(a0.x, a0.y), fmaxf(a0.z, a0.w)),
                    fmaxf(fmaxf(a1.x, a1.y), fmaxf(a1.z, a1.w)));
#pragma unroll
    for (int off = 4; off; off >>= 1) m = fmaxf(m, __shfl_xor_sync(0xffffffffu, m, off));
    float s = __expf(a0.x - m) + __expf(a0.y - m) + __expf(a0.z - m) + __expf(a0.w - m) +
              __expf(a1.x - m) + __expf(a1.y - m) + __expf(a1.z - m) + __expf(a1.w - m);
#pragma unroll
    for (int off = 4; off; off >>= 1) s += __shfl_xor_sync(0xffffffffu, s, off);
    float lse = m + __logf(s);
    a0.x -= lse; a0.y -= lse; a0.z -= lse; a0.w -= lse;
    a1.x -= lse; a1.y -= lse; a1.z -= lse; a1.w -= lse;
    Out[(size_t)g * 16 + lane * 2] = a0;
    Out[(size_t)g * 16 + lane * 2 + 1] = a1;
}

// ---------------------------------------------------------------------------
extern "C" void kernel_launch(void* const* d_in, const int* in_sizes, int n_in,
                              void* d_out, int out_size) {
    const float* x  = (const float*)d_in[0];
    const void*  ei = d_in[1];
    const float* w1 = (const float*)d_in[2];
    const float* b1 = (const float*)d_in[3];
    const float* c1 = (const float*)d_in[4];
    const float* w2 = (const float*)d_in[5];
    const float* b2 = (const float*)d_in[6];
    const float* c2 = (const float*)d_in[7];
    float4* out     = (float4*)d_out;

    int N = in_sizes[0] / 128;
    int E = in_sizes[1] / 2;

    const int SMEM1 = 2 * (10240 + 128 * 80);  // 40960
    const int SMEM2 = 2 * (10240 + 64 * 80);   // 30720
    cudaFuncSetAttribute((const void*)kan_gemm_mma<128>,
                         cudaFuncAttributeMaxDynamicSharedMemorySize, SMEM1);
    cudaFuncSetAttribute((const void*)kan_gemm_mma<64>,
                         cudaFuncAttributeMaxDynamicSharedMemorySize, SMEM2);

    // fork-join: CSR build on side stream, weights+GEMM1 on main (capture) stream.
    // Stream/events created per call and deliberately not destroyed (capture).
    cudaStream_t s1;
    cudaStreamCreateWithFlags(&s1, cudaStreamNonBlocking);
    cudaEvent_t evF, evJ;
    cudaEventCreateWithFlags(&evF, cudaEventDisableTiming);
    cudaEventCreateWithFlags(&evJ, cudaEventDisableTiming);

    cudaEventRecord(evF, 0);
    cudaStreamWaitEvent(s1, evF, 0);

    // ---- side stream: CSR chain (decodes edge_index in place) ----
    zero_int2<<<(N + 255) / 256, 256, 0, s1>>>(N);
    detect_dtype<<<1, 32, 0, s1>>>((const int*)ei);
    int quads = (E + 3) / 4;
    hist_kernel<<<(quads + 255) / 256, 256, 0, s1>>>(ei, E, N);
    int nb = (N + 1023) / 1024;
    scan_partials<<<nb, 1024, 0, s1>>>(N);
    add_offsets<<<nb, 1024, 0, s1>>>(N);
    build_csr<<<(quads + 255) / 256, 256, 0, s1>>>(ei, E, N);
    cudaEventRecord(evJ, s1);

    // ---- main stream: weights + GEMM1 (overlapped with CSR) ----
    fuse_weights_t<<<(384 * 128 + 384 * 64 + 255) / 256, 256>>>(w1, c1, w2, c2);
    int tiles = (N + 127) / 128;
    kan_gemm_mma<128><<<tiles, 256, SMEM1>>>(x, b1, N);

    // join: gathers need both CSR and h1
    cudaStreamWaitEvent(0, evJ, 0);

    // aggregate 1 (mean)
    gather_mean1<<<(N + 15) / 16, 256>>>(N);

    // layer 2
    kan_gemm_mma<64><<<tiles, 256, SMEM2>>>(nullptr, b2, N);

    // aggregate 2 (mean) + log_softmax, straight into d_out
    gather_mean_lsm<<<(N + 31) / 32, 256>>>(out, N);
}